// round 1
// baseline (speedup 1.0000x reference)
#include <cuda_runtime.h>
#include <cuda_fp16.h>
#include <stdint.h>

#define B_   4
#define L_   2048
#define CIN  256
#define HID_ 1024
#define NH   8
#define HD   128
#define OUT_ 256
#define MTOT (B_*L_)   // 8192

// ---------------- scratch (device globals; no allocs allowed) ----------------
__device__ __align__(16) __half g_Pk[(size_t)B_*NH*L_*HD];
__device__ __align__(16) __half g_Pq[(size_t)B_*NH*L_*HD];
__device__ __align__(16) __half g_Pv[(size_t)B_*NH*L_*HD];
__device__ __align__(16) __half g_attn[(size_t)B_*NH*L_*L_];   // 268 MB fp16
__device__ __align__(16) float  g_O[(size_t)B_*L_*HID_];       // [b][l][j*8+h]

// ---------------- mma / ldmatrix helpers ----------------
__device__ __forceinline__ uint32_t cvta_s(const void* p){
    return (uint32_t)__cvta_generic_to_shared(p);
}
__device__ __forceinline__ void ldm_x4(uint32_t* r, uint32_t a){
    asm volatile("ldmatrix.sync.aligned.m8n8.x4.shared.b16 {%0,%1,%2,%3},[%4];\n"
        :"=r"(r[0]),"=r"(r[1]),"=r"(r[2]),"=r"(r[3]):"r"(a));
}
__device__ __forceinline__ void ldm_x4t(uint32_t* r, uint32_t a){
    asm volatile("ldmatrix.sync.aligned.m8n8.x4.trans.shared.b16 {%0,%1,%2,%3},[%4];\n"
        :"=r"(r[0]),"=r"(r[1]),"=r"(r[2]),"=r"(r[3]):"r"(a));
}
__device__ __forceinline__ void mma_f16(float* d, const uint32_t* a, const uint32_t* b, const float* c){
    asm volatile("mma.sync.aligned.m16n8k16.row.col.f32.f16.f16.f32 "
        "{%0,%1,%2,%3},{%4,%5,%6,%7},{%8,%9},{%10,%11,%12,%13};\n"
        :"=f"(d[0]),"=f"(d[1]),"=f"(d[2]),"=f"(d[3])
        :"r"(a[0]),"r"(a[1]),"r"(a[2]),"r"(a[3]),"r"(b[0]),"r"(b[1]),
         "f"(c[0]),"f"(c[1]),"f"(c[2]),"f"(c[3]));
}
__device__ __forceinline__ void split2h(float x, __half& hi, __half& lo){
    hi = __float2half_rn(x);
    lo = __float2half_rn(x - __half2float(hi));
}

// =============================================================================
// Kernel 1/4: split-fp16 TN GEMM  C[M,N] = A[M,K] @ W[N,K]^T + bias
//   mode 0: write fp16 into g_P{which} with head layout  P[b][h=n&7][l][d=n>>3]
//   mode 1: write fp32 C row-major (final output)
//   W is loaded pre-scaled by 256 (keeps lo-halves normal in fp16); undone in
//   the epilogue. A==nullptr means "read from g_O".
// =============================================================================
__global__ __launch_bounds__(256,1) void gemm_split_kernel(
    const float* __restrict__ A, const float* __restrict__ W,
    const float* __restrict__ bias, float* __restrict__ Cout,
    int M, int N, int K, int mode, int which)
{
    __shared__ __align__(16) __half Ah[128][40];
    __shared__ __align__(16) __half Al[128][40];
    __shared__ __align__(16) __half Bh[128][40];
    __shared__ __align__(16) __half Bl[128][40];

    const float* Ap = A ? A : (const float*)g_O;
    const int tid  = threadIdx.x;
    const int lane = tid & 31, wid = tid >> 5;
    const int wm = wid >> 1, wn = wid & 1;          // warp tile 32(m) x 64(n)
    const int m0 = blockIdx.y * 128, n0 = blockIdx.x * 128;

    float acc[2][8][4];
    #pragma unroll
    for (int i=0;i<2;i++){ for(int j=0;j<8;j++){ for(int e=0;e<4;e++) acc[i][j][e]=0.f; } }

    for (int kk=0; kk<K; kk+=32) {
        __syncthreads();
        #pragma unroll
        for (int it=0; it<4; it++){
            int idx = tid + it*256;                 // 1024 float4 total
            int r = idx >> 3, c = (idx & 7) * 4;
            float4 va = *(const float4*)(Ap + (size_t)(m0+r)*K + kk + c);
            __half h,l;
            split2h(va.x,h,l); Ah[r][c+0]=h; Al[r][c+0]=l;
            split2h(va.y,h,l); Ah[r][c+1]=h; Al[r][c+1]=l;
            split2h(va.z,h,l); Ah[r][c+2]=h; Al[r][c+2]=l;
            split2h(va.w,h,l); Ah[r][c+3]=h; Al[r][c+3]=l;
            float4 vb = *(const float4*)(W + (size_t)(n0+r)*K + kk + c);
            split2h(vb.x*256.f,h,l); Bh[r][c+0]=h; Bl[r][c+0]=l;
            split2h(vb.y*256.f,h,l); Bh[r][c+1]=h; Bl[r][c+1]=l;
            split2h(vb.z*256.f,h,l); Bh[r][c+2]=h; Bl[r][c+2]=l;
            split2h(vb.w*256.f,h,l); Bh[r][c+3]=h; Bl[r][c+3]=l;
        }
        __syncthreads();
        #pragma unroll
        for (int ks=0; ks<2; ks++){
            uint32_t ah[2][4], al[2][4];
            #pragma unroll
            for (int mt=0; mt<2; mt++){
                ldm_x4(ah[mt], cvta_s(&Ah[wm*32+mt*16+(lane&15)][ks*16+(lane>>4)*8]));
                ldm_x4(al[mt], cvta_s(&Al[wm*32+mt*16+(lane&15)][ks*16+(lane>>4)*8]));
            }
            uint32_t bh[8][2], bl[8][2];
            #pragma unroll
            for (int p=0;p<4;p++){
                uint32_t r4[4];
                ldm_x4(r4, cvta_s(&Bh[wn*64+p*16+(lane&15)][ks*16+(lane>>4)*8]));
                bh[2*p][0]=r4[0]; bh[2*p][1]=r4[2]; bh[2*p+1][0]=r4[1]; bh[2*p+1][1]=r4[3];
                ldm_x4(r4, cvta_s(&Bl[wn*64+p*16+(lane&15)][ks*16+(lane>>4)*8]));
                bl[2*p][0]=r4[0]; bl[2*p][1]=r4[2]; bl[2*p+1][0]=r4[1]; bl[2*p+1][1]=r4[3];
            }
            #pragma unroll
            for (int mt=0; mt<2; mt++){
                #pragma unroll
                for (int nt=0; nt<8; nt++){
                    mma_f16(acc[mt][nt], ah[mt], bh[nt], acc[mt][nt]);   // hi*hi
                    mma_f16(acc[mt][nt], ah[mt], bl[nt], acc[mt][nt]);   // hi*lo
                    mma_f16(acc[mt][nt], al[mt], bh[nt], acc[mt][nt]);   // lo*hi
                }
            }
        }
    }
    const float inv = 1.f/256.f;
    __half* P = (which==0)? g_Pk : (which==1)? g_Pq : g_Pv;
    #pragma unroll
    for (int mt=0; mt<2; mt++){
        #pragma unroll
        for (int nt=0; nt<8; nt++){
            #pragma unroll
            for (int e=0; e<4; e++){
                int m = m0 + wm*32 + mt*16 + (lane>>2) + (e>>1)*8;
                int n = n0 + wn*64 + nt*8 + (lane&3)*2 + (e&1);
                float v = acc[mt][nt][e]*inv + bias[n];
                if (mode==0){
                    int b = m >> 11, l = m & 2047;
                    int h = n & 7,  d = n >> 3;      // hidden = d*8 + h (head LAST)
                    P[(((size_t)(b*NH+h))*L_ + l)*HD + d] = __float2half_rn(v);
                } else {
                    Cout[(size_t)m*N + n] = v;
                }
            }
        }
    }
}

// =============================================================================
// Kernel 2: per-tile scores for ALL 8 heads + softmax over heads -> g_attn
//   Tile: 64(i) x 64(k). 8 warps, warp tile 16x32, acc[8 heads][16] in regs.
// =============================================================================
__global__ __launch_bounds__(256,1) void score_softmax_kernel()
{
    __shared__ __align__(16) __half Ks[64][136];
    __shared__ __align__(16) __half Qs[64][136];
    const int b  = blockIdx.z;
    const int i0 = blockIdx.y * 64, k0 = blockIdx.x * 64;
    const int tid = threadIdx.x, lane = tid & 31, wid = tid >> 5;
    const int wi = wid >> 1, wk = wid & 1;          // warp tile 16(i) x 32(k)

    float acc[NH][4][4];
    #pragma unroll
    for (int h=0;h<NH;h++){ for(int nt=0;nt<4;nt++){ for(int e=0;e<4;e++) acc[h][nt][e]=0.f; } }

    #pragma unroll
    for (int h=0; h<NH; h++){
        const __half* Kp = g_Pk + (((size_t)(b*NH+h))*L_ + i0)*HD;
        const __half* Qp = g_Pq + (((size_t)(b*NH+h))*L_ + k0)*HD;
        __syncthreads();
        #pragma unroll
        for (int it=0; it<4; it++){
            int idx = tid + it*256;                 // 64 rows x 16 uint4
            int r = idx >> 4, c = (idx & 15) * 8;
            *(uint4*)&Ks[r][c] = *(const uint4*)(Kp + (size_t)r*HD + c);
            *(uint4*)&Qs[r][c] = *(const uint4*)(Qp + (size_t)r*HD + c);
        }
        __syncthreads();
        #pragma unroll
        for (int ks=0; ks<8; ks++){
            uint32_t af[4];
            ldm_x4(af, cvta_s(&Ks[wi*16+(lane&15)][ks*16+(lane>>4)*8]));
            uint32_t bf[4][2];
            #pragma unroll
            for (int p=0;p<2;p++){
                uint32_t r4[4];
                ldm_x4(r4, cvta_s(&Qs[wk*32+p*16+(lane&15)][ks*16+(lane>>4)*8]));
                bf[2*p][0]=r4[0]; bf[2*p][1]=r4[2]; bf[2*p+1][0]=r4[1]; bf[2*p+1][1]=r4[3];
            }
            #pragma unroll
            for (int nt=0; nt<4; nt++) mma_f16(acc[h][nt], af, bf[nt], acc[h][nt]);
        }
    }

    // softmax over heads per (i,k); each thread owns the same (i,k) for all h
    const float sc = 0.08838834764831845f;          // 1/sqrt(128)
    #pragma unroll
    for (int nt=0; nt<4; nt++){
        #pragma unroll
        for (int e=0; e<4; e++){
            float m = -1e30f;
            #pragma unroll
            for (int h=0;h<NH;h++){ float s = acc[h][nt][e]*sc; acc[h][nt][e]=s; m=fmaxf(m,s); }
            float sum = 0.f;
            #pragma unroll
            for (int h=0;h<NH;h++){ float ex = __expf(acc[h][nt][e]-m); acc[h][nt][e]=ex; sum+=ex; }
            float rs = 1.f/sum;
            int i = i0 + wi*16 + (lane>>2) + (e>>1)*8;
            int k = k0 + wk*32 + nt*8 + (lane&3)*2 + (e&1);
            #pragma unroll
            for (int h=0;h<NH;h++)
                g_attn[(((size_t)(b*NH+h))*L_ + i)*L_ + k] = __float2half_rn(acc[h][nt][e]*rs);
        }
    }
}

// =============================================================================
// Kernel 3: O[b][k][j*8+h] = sum_i attn[b,h,i,k] * Pv[b,h,i,j]   (A^T @ V)
//   CTA per (b,h,k_tile=128); trans-ldmatrix for both operands.
// =============================================================================
__global__ __launch_bounds__(256,1) void av_kernel()
{
    __shared__ __align__(16) __half As[32][136];    // attn [i][k-tile]
    __shared__ __align__(16) __half Vs[32][136];    // V    [i][j]
    const int b = blockIdx.z, h = blockIdx.y;
    const int k0 = blockIdx.x * 128;
    const int tid = threadIdx.x, lane = tid & 31, wid = tid >> 5;
    const int wm = wid >> 1, wn = wid & 1;          // warp tile 32(k) x 64(j)

    float acc[2][8][4];
    #pragma unroll
    for (int i=0;i<2;i++){ for(int j=0;j<8;j++){ for(int e=0;e<4;e++) acc[i][j][e]=0.f; } }

    const __half* Ab = g_attn + ((size_t)(b*NH+h))*L_*L_;
    const __half* Vb = g_Pv   + ((size_t)(b*NH+h))*L_*HD;

    for (int i0=0; i0<L_; i0+=32){
        __syncthreads();
        #pragma unroll
        for (int it=0; it<2; it++){
            int idx = tid + it*256;                 // 32 rows x 16 uint4
            int r = idx >> 4, c = (idx & 15) * 8;
            *(uint4*)&As[r][c] = *(const uint4*)(Ab + (size_t)(i0+r)*L_ + k0 + c);
            *(uint4*)&Vs[r][c] = *(const uint4*)(Vb + (size_t)(i0+r)*HD + c);
        }
        __syncthreads();
        #pragma unroll
        for (int ks=0; ks<2; ks++){
            uint32_t af[2][4];
            #pragma unroll
            for (int mt=0; mt<2; mt++){
                // A-frag (m=k dim) from As stored [i][k]: transposed load
                ldm_x4t(af[mt], cvta_s(
                    &As[ks*16 + (lane&7) + ((lane>>4)&1)*8][wm*32 + mt*16 + ((lane>>3)&1)*8]));
            }
            uint32_t bf[8][2];
            #pragma unroll
            for (int p=0;p<4;p++){
                uint32_t r4[4];
                // B-frag (n=j dim) from Vs stored [i][j]: transposed load
                ldm_x4t(r4, cvta_s(
                    &Vs[ks*16 + (lane&7) + ((lane>>3)&1)*8][wn*64 + p*16 + ((lane>>4)&1)*8]));
                bf[2*p][0]=r4[0]; bf[2*p][1]=r4[1]; bf[2*p+1][0]=r4[2]; bf[2*p+1][1]=r4[3];
            }
            #pragma unroll
            for (int mt=0; mt<2; mt++){
                #pragma unroll
                for (int nt=0; nt<8; nt++)
                    mma_f16(acc[mt][nt], af[mt], bf[nt], acc[mt][nt]);
            }
        }
    }
    #pragma unroll
    for (int mt=0; mt<2; mt++){
        #pragma unroll
        for (int nt=0; nt<8; nt++){
            #pragma unroll
            for (int e=0; e<4; e++){
                int k = k0 + wm*32 + mt*16 + (lane>>2) + (e>>1)*8;
                int j = wn*64 + nt*8 + (lane&3)*2 + (e&1);
                g_O[((size_t)b*L_ + k)*HID_ + j*NH + h] = acc[mt][nt][e];
            }
        }
    }
}

// =============================================================================
extern "C" void kernel_launch(void* const* d_in, const int* in_sizes, int n_in,
                              void* d_out, int out_size)
{
    const float* KEY   = (const float*)d_in[0];
    const float* VALUE = (const float*)d_in[1];
    const float* QUERY = (const float*)d_in[2];
    const float* W_w   = (const float*)d_in[3];
    const float* W_b   = (const float*)d_in[4];
    const float* Wv_w  = (const float*)d_in[5];
    const float* Wv_b  = (const float*)d_in[6];
    const float* Wo_w  = (const float*)d_in[7];
    const float* Wo_b  = (const float*)d_in[8];
    float* out = (float*)d_out;

    dim3 blk(256);
    // projections (split-fp16, fp32-accurate) -> per-head fp16 layout
    gemm_split_kernel<<<dim3(8,64), blk>>>(KEY,   W_w,  W_b,  nullptr, MTOT, HID_, CIN, 0, 0);
    gemm_split_kernel<<<dim3(8,64), blk>>>(QUERY, W_w,  W_b,  nullptr, MTOT, HID_, CIN, 0, 1);
    gemm_split_kernel<<<dim3(8,64), blk>>>(VALUE, Wv_w, Wv_b, nullptr, MTOT, HID_, CIN, 0, 2);
    // scores for all heads + softmax over heads
    score_softmax_kernel<<<dim3(L_/64, L_/64, B_), blk>>>();
    // attn^T @ V per (b,h)
    av_kernel<<<dim3(L_/128, NH, B_), blk>>>();
    // final projection
    gemm_split_kernel<<<dim3(2,64), blk>>>(nullptr, Wo_w, Wo_b, out, MTOT, OUT_, HID_, 1, 0);
}

// round 2
// speedup vs baseline: 1.4052x; 1.4052x over previous
#include <cuda_runtime.h>
#include <cuda_fp16.h>
#include <stdint.h>

#define B_   4
#define L_   2048
#define CIN  256
#define HID_ 1024
#define NH   8
#define HD   128
#define OUT_ 256
#define MTOT (B_*L_)   // 8192

// ---------------- scratch (device globals; no allocs allowed) ----------------
__device__ __align__(16) __half g_Pk[(size_t)B_*NH*L_*HD];
__device__ __align__(16) __half g_Pq[(size_t)B_*NH*L_*HD];     // pre-scaled by 1/sqrt(128)
__device__ __align__(16) __half g_Pv[(size_t)B_*NH*L_*HD];
__device__ __align__(16) __half g_attn[(size_t)B_*NH*L_*L_];   // 268 MB fp16
__device__ __align__(16) float  g_OT[(size_t)B_*HID_*L_];      // O^T: [b][j*8+h][l]

// ---------------- mma / ldmatrix / cp.async helpers ----------------
__device__ __forceinline__ uint32_t cvta_s(const void* p){
    return (uint32_t)__cvta_generic_to_shared(p);
}
__device__ __forceinline__ void ldm_x4(uint32_t* r, uint32_t a){
    asm volatile("ldmatrix.sync.aligned.m8n8.x4.shared.b16 {%0,%1,%2,%3},[%4];\n"
        :"=r"(r[0]),"=r"(r[1]),"=r"(r[2]),"=r"(r[3]):"r"(a));
}
__device__ __forceinline__ void ldm_x4t(uint32_t* r, uint32_t a){
    asm volatile("ldmatrix.sync.aligned.m8n8.x4.trans.shared.b16 {%0,%1,%2,%3},[%4];\n"
        :"=r"(r[0]),"=r"(r[1]),"=r"(r[2]),"=r"(r[3]):"r"(a));
}
__device__ __forceinline__ void mma_f16(float* d, const uint32_t* a, const uint32_t* b, const float* c){
    asm volatile("mma.sync.aligned.m16n8k16.row.col.f32.f16.f16.f32 "
        "{%0,%1,%2,%3},{%4,%5,%6,%7},{%8,%9},{%10,%11,%12,%13};\n"
        :"=f"(d[0]),"=f"(d[1]),"=f"(d[2]),"=f"(d[3])
        :"r"(a[0]),"r"(a[1]),"r"(a[2]),"r"(a[3]),"r"(b[0]),"r"(b[1]),
         "f"(c[0]),"f"(c[1]),"f"(c[2]),"f"(c[3]));
}
// fp16-accumulator mma (halves score-kernel accumulator registers)
__device__ __forceinline__ void mma_f16h(uint32_t* d, const uint32_t* a, const uint32_t* b){
    asm volatile("mma.sync.aligned.m16n8k16.row.col.f16.f16.f16.f16 "
        "{%0,%1},{%2,%3,%4,%5},{%6,%7},{%8,%9};\n"
        :"=r"(d[0]),"=r"(d[1])
        :"r"(a[0]),"r"(a[1]),"r"(a[2]),"r"(a[3]),"r"(b[0]),"r"(b[1]),
         "r"(d[0]),"r"(d[1]));
}
__device__ __forceinline__ void cp16(void* dst_smem, const void* src){
    uint32_t d = cvta_s(dst_smem);
    asm volatile("cp.async.cg.shared.global [%0],[%1],16;\n"::"r"(d),"l"(src));
}
#define CP_COMMIT() asm volatile("cp.async.commit_group;\n")
#define CP_WAIT(n)  asm volatile("cp.async.wait_group %0;\n"::"n"(n))

__device__ __forceinline__ void split2h(float x, __half& hi, __half& lo){
    hi = __float2half_rn(x);
    lo = __float2half_rn(x - __half2float(hi));
}

// =============================================================================
// Kernel 1: split-fp16 TN GEMM  C[M,N] = A[M,K] @ W[N,K]^T + bias
//   mode 0: A from gmem fp32 [M,K]; write fp16 head layout P[b][h=n&7][l][d=n>>3]
//           (which==1 i.e. Q gets pre-scaled by 1/sqrt(128))
//   mode 1: A from g_OT (fp32, [b][hid][l] transposed); write fp32 C row-major
// =============================================================================
__global__ __launch_bounds__(256,1) void gemm_split_kernel(
    const float* __restrict__ A, const float* __restrict__ W,
    const float* __restrict__ bias, float* __restrict__ Cout,
    int M, int N, int K, int mode, int which)
{
    __shared__ __align__(16) __half Ah[128][40];
    __shared__ __align__(16) __half Al[128][40];
    __shared__ __align__(16) __half Bh[128][40];
    __shared__ __align__(16) __half Bl[128][40];

    const int tid  = threadIdx.x;
    const int lane = tid & 31, wid = tid >> 5;
    const int wm = wid >> 1, wn = wid & 1;          // warp tile 32(m) x 64(n)
    const int m0 = blockIdx.y * 128, n0 = blockIdx.x * 128;

    float acc[2][8][4];
    #pragma unroll
    for (int i=0;i<2;i++){ for(int j=0;j<8;j++){ for(int e=0;e<4;e++) acc[i][j][e]=0.f; } }

    for (int kk=0; kk<K; kk+=32) {
        __syncthreads();
        if (mode==0){
            #pragma unroll
            for (int it=0; it<4; it++){
                int idx = tid + it*256;             // 1024 float4 total
                int r = idx >> 3, c = (idx & 7) * 4;
                float4 va = *(const float4*)(A + (size_t)(m0+r)*K + kk + c);
                __half h,l;
                split2h(va.x,h,l); Ah[r][c+0]=h; Al[r][c+0]=l;
                split2h(va.y,h,l); Ah[r][c+1]=h; Al[r][c+1]=l;
                split2h(va.z,h,l); Ah[r][c+2]=h; Al[r][c+2]=l;
                split2h(va.w,h,l); Ah[r][c+3]=h; Al[r][c+3]=l;
            }
        } else {
            // A tile from g_OT: [b][hid=kk+r][l = l0+c], transposed into Ah[l][k]
            int b  = m0 >> 11, l0 = m0 & 2047;
            #pragma unroll
            for (int it=0; it<4; it++){
                int idx = tid + it*256;             // 32 rows(k) x 32 float4(l)
                int r = idx >> 5, c = (idx & 31) * 4;
                float4 va = *(const float4*)(g_OT + ((size_t)b*HID_ + kk + r)*L_ + l0 + c);
                __half h,l;
                split2h(va.x,h,l); Ah[c+0][r]=h; Al[c+0][r]=l;
                split2h(va.y,h,l); Ah[c+1][r]=h; Al[c+1][r]=l;
                split2h(va.z,h,l); Ah[c+2][r]=h; Al[c+2][r]=l;
                split2h(va.w,h,l); Ah[c+3][r]=h; Al[c+3][r]=l;
            }
        }
        #pragma unroll
        for (int it=0; it<4; it++){
            int idx = tid + it*256;
            int r = idx >> 3, c = (idx & 7) * 4;
            float4 vb = *(const float4*)(W + (size_t)(n0+r)*K + kk + c);
            __half h,l;
            split2h(vb.x*256.f,h,l); Bh[r][c+0]=h; Bl[r][c+0]=l;
            split2h(vb.y*256.f,h,l); Bh[r][c+1]=h; Bl[r][c+1]=l;
            split2h(vb.z*256.f,h,l); Bh[r][c+2]=h; Bl[r][c+2]=l;
            split2h(vb.w*256.f,h,l); Bh[r][c+3]=h; Bl[r][c+3]=l;
        }
        __syncthreads();
        #pragma unroll
        for (int ks=0; ks<2; ks++){
            uint32_t ah[2][4], al[2][4];
            #pragma unroll
            for (int mt=0; mt<2; mt++){
                ldm_x4(ah[mt], cvta_s(&Ah[wm*32+mt*16+(lane&15)][ks*16+(lane>>4)*8]));
                ldm_x4(al[mt], cvta_s(&Al[wm*32+mt*16+(lane&15)][ks*16+(lane>>4)*8]));
            }
            uint32_t bh[8][2], bl[8][2];
            #pragma unroll
            for (int p=0;p<4;p++){
                uint32_t r4[4];
                ldm_x4(r4, cvta_s(&Bh[wn*64+p*16+(lane&15)][ks*16+(lane>>4)*8]));
                bh[2*p][0]=r4[0]; bh[2*p][1]=r4[2]; bh[2*p+1][0]=r4[1]; bh[2*p+1][1]=r4[3];
                ldm_x4(r4, cvta_s(&Bl[wn*64+p*16+(lane&15)][ks*16+(lane>>4)*8]));
                bl[2*p][0]=r4[0]; bl[2*p][1]=r4[2]; bl[2*p+1][0]=r4[1]; bl[2*p+1][1]=r4[3];
            }
            #pragma unroll
            for (int mt=0; mt<2; mt++){
                #pragma unroll
                for (int nt=0; nt<8; nt++){
                    mma_f16(acc[mt][nt], ah[mt], bh[nt], acc[mt][nt]);   // hi*hi
                    mma_f16(acc[mt][nt], ah[mt], bl[nt], acc[mt][nt]);   // hi*lo
                    mma_f16(acc[mt][nt], al[mt], bh[nt], acc[mt][nt]);   // lo*hi
                }
            }
        }
    }
    const float inv = 1.f/256.f;
    const float qs  = (which==1) ? 0.08838834764831845f : 1.0f;  // 1/sqrt(128)
    __half* P = (which==0)? g_Pk : (which==1)? g_Pq : g_Pv;
    #pragma unroll
    for (int mt=0; mt<2; mt++){
        #pragma unroll
        for (int nt=0; nt<8; nt++){
            #pragma unroll
            for (int e=0; e<4; e++){
                int m = m0 + wm*32 + mt*16 + (lane>>2) + (e>>1)*8;
                int n = n0 + wn*64 + nt*8 + (lane&3)*2 + (e&1);
                float v = acc[mt][nt][e]*inv + bias[n];
                if (mode==0){
                    int b = m >> 11, l = m & 2047;
                    int h = n & 7,  d = n >> 3;      // hidden = d*8 + h (head LAST)
                    P[(((size_t)(b*NH+h))*L_ + l)*HD + d] = __float2half_rn(v*qs);
                } else {
                    Cout[(size_t)m*N + n] = v;
                }
            }
        }
    }
}

// =============================================================================
// Kernel 2: scores for ALL 8 heads (fp16 acc) + softmax over heads -> g_attn
//   Tile 64(i) x 64(k); cp.async double-buffered over heads; 2 CTAs/SM.
// =============================================================================
__global__ __launch_bounds__(256,2) void score_softmax_kernel()
{
    extern __shared__ __align__(16) __half s_dyn[];
    __half (*Ks)[64][136] = (__half(*)[64][136])(s_dyn);
    __half (*Qs)[64][136] = (__half(*)[64][136])(s_dyn + 2*64*136);

    const int b  = blockIdx.z;
    const int i0 = blockIdx.y * 64, k0 = blockIdx.x * 64;
    const int tid = threadIdx.x, lane = tid & 31, wid = tid >> 5;
    const int wi = wid >> 1, wk = wid & 1;          // warp tile 16(i) x 32(k)

    uint32_t acc[NH][4][2];                          // fp16x2 accumulators
    #pragma unroll
    for (int h=0;h<NH;h++){ for(int nt=0;nt<4;nt++){ acc[h][nt][0]=0u; acc[h][nt][1]=0u; } }

    const int lr = tid >> 4, lc = (tid & 15) * 8;   // per-thread cp.async coords

    // prologue: head 0 into buffer 0
    {
        const __half* Kp = g_Pk + (((size_t)(b*NH+0))*L_ + i0)*HD;
        const __half* Qp = g_Pq + (((size_t)(b*NH+0))*L_ + k0)*HD;
        #pragma unroll
        for (int it=0; it<4; it++){
            int r = lr + it*16;
            cp16(&Ks[0][r][lc], Kp + (size_t)r*HD + lc);
            cp16(&Qs[0][r][lc], Qp + (size_t)r*HD + lc);
        }
        CP_COMMIT();
    }

    #pragma unroll
    for (int h=0; h<NH; h++){
        if (h < NH-1){
            const __half* Kp = g_Pk + (((size_t)(b*NH+h+1))*L_ + i0)*HD;
            const __half* Qp = g_Pq + (((size_t)(b*NH+h+1))*L_ + k0)*HD;
            int nb = (h+1)&1;
            #pragma unroll
            for (int it=0; it<4; it++){
                int r = lr + it*16;
                cp16(&Ks[nb][r][lc], Kp + (size_t)r*HD + lc);
                cp16(&Qs[nb][r][lc], Qp + (size_t)r*HD + lc);
            }
            CP_COMMIT();
            CP_WAIT(1);
        } else {
            CP_WAIT(0);
        }
        __syncthreads();
        const int cb = h&1;
        #pragma unroll
        for (int ks=0; ks<8; ks++){
            uint32_t af[4];
            ldm_x4(af, cvta_s(&Ks[cb][wi*16+(lane&15)][ks*16+(lane>>4)*8]));
            uint32_t bf[4][2];
            #pragma unroll
            for (int p=0;p<2;p++){
                uint32_t r4[4];
                ldm_x4(r4, cvta_s(&Qs[cb][wk*32+p*16+(lane&15)][ks*16+(lane>>4)*8]));
                bf[2*p][0]=r4[0]; bf[2*p][1]=r4[2]; bf[2*p+1][0]=r4[1]; bf[2*p+1][1]=r4[3];
            }
            #pragma unroll
            for (int nt=0; nt<4; nt++) mma_f16h(acc[h][nt], af, bf[nt]);
        }
        __syncthreads();
    }

    // softmax over heads (logits ~0.1 magnitude: no max-subtraction needed)
    #pragma unroll
    for (int nt=0; nt<4; nt++){
        #pragma unroll
        for (int p=0; p<2; p++){
            float ex[NH][2]; float s0=0.f, s1=0.f;
            #pragma unroll
            for (int h=0;h<NH;h++){
                float2 f = __half22float2(*(__half2*)&acc[h][nt][p]);
                float e0 = __expf(f.x), e1 = __expf(f.y);
                ex[h][0]=e0; ex[h][1]=e1; s0+=e0; s1+=e1;
            }
            float r0 = 1.f/s0, r1 = 1.f/s1;
            int i = i0 + wi*16 + (lane>>2) + p*8;
            int k = k0 + wk*32 + nt*8 + (lane&3)*2;
            #pragma unroll
            for (int h=0;h<NH;h++){
                __half2 v = __floats2half2_rn(ex[h][0]*r0, ex[h][1]*r1);
                *(__half2*)&g_attn[(((size_t)(b*NH+h))*L_ + i)*L_ + k] = v;
            }
        }
    }
}

// =============================================================================
// Kernel 3: O^T[b][j*8+h][k] = sum_i attn[b,h,i,k] * Pv[b,h,i,j]
//   CTA per (k-tile=128, h, b); m-dim = j(128), n-dim = k(128);
//   cp.async double-buffered over i-tiles of 64; coalesced float2 stores.
// =============================================================================
__global__ __launch_bounds__(256,2) void av_kernel()
{
    extern __shared__ __align__(16) __half s_dyn2[];
    __half (*As)[64][136] = (__half(*)[64][136])(s_dyn2);             // attn [i][k]
    __half (*Vs)[64][136] = (__half(*)[64][136])(s_dyn2 + 2*64*136);  // V    [i][j]

    const int b = blockIdx.z, h = blockIdx.y;
    const int k0 = blockIdx.x * 128;
    const int tid = threadIdx.x, lane = tid & 31, wid = tid >> 5;
    const int wj = wid >> 1, wk = wid & 1;          // warp tile 32(j) x 64(k)

    float acc[2][8][4];
    #pragma unroll
    for (int i=0;i<2;i++){ for(int j=0;j<8;j++){ for(int e=0;e<4;e++) acc[i][j][e]=0.f; } }

    const __half* Ab = g_attn + ((size_t)(b*NH+h))*L_*L_;
    const __half* Vb = g_Pv   + ((size_t)(b*NH+h))*L_*HD;

    const int lr = tid >> 4, lc = (tid & 15) * 8;

    // prologue
    #pragma unroll
    for (int it=0; it<4; it++){
        int r = lr + it*16;
        cp16(&As[0][r][lc], Ab + (size_t)r*L_ + k0 + lc);
        cp16(&Vs[0][r][lc], Vb + (size_t)r*HD + lc);
    }
    CP_COMMIT();

    for (int s=0; s<L_/64; s++){
        if (s < L_/64-1){
            int i1 = (s+1)*64, nb = (s+1)&1;
            #pragma unroll
            for (int it=0; it<4; it++){
                int r = lr + it*16;
                cp16(&As[nb][r][lc], Ab + (size_t)(i1+r)*L_ + k0 + lc);
                cp16(&Vs[nb][r][lc], Vb + (size_t)(i1+r)*HD + lc);
            }
            CP_COMMIT();
            CP_WAIT(1);
        } else {
            CP_WAIT(0);
        }
        __syncthreads();
        const int cb = s&1;
        #pragma unroll
        for (int ks=0; ks<4; ks++){
            uint32_t af[2][4];
            #pragma unroll
            for (int mt=0; mt<2; mt++){
                // A-frag (m=j) from Vs[i][j]: transposed load
                ldm_x4t(af[mt], cvta_s(
                    &Vs[cb][ks*16 + (lane&7) + ((lane>>4)&1)*8][wj*32 + mt*16 + ((lane>>3)&1)*8]));
            }
            uint32_t bf[8][2];
            #pragma unroll
            for (int p=0;p<4;p++){
                uint32_t r4[4];
                // B-frag (n=k) from As[i][k]: transposed load
                ldm_x4t(r4, cvta_s(
                    &As[cb][ks*16 + (lane&7) + ((lane>>3)&1)*8][wk*64 + p*16 + ((lane>>4)&1)*8]));
                bf[2*p][0]=r4[0]; bf[2*p][1]=r4[1]; bf[2*p+1][0]=r4[2]; bf[2*p+1][1]=r4[3];
            }
            #pragma unroll
            for (int mt=0; mt<2; mt++){
                #pragma unroll
                for (int nt=0; nt<8; nt++)
                    mma_f16(acc[mt][nt], af[mt], bf[nt], acc[mt][nt]);
            }
        }
        __syncthreads();
    }
    #pragma unroll
    for (int mt=0; mt<2; mt++){
        #pragma unroll
        for (int nt=0; nt<8; nt++){
            #pragma unroll
            for (int p=0; p<2; p++){
                int j = wj*32 + mt*16 + (lane>>2) + p*8;
                int k = k0 + wk*64 + nt*8 + (lane&3)*2;
                float2 v = make_float2(acc[mt][nt][p*2+0], acc[mt][nt][p*2+1]);
                *(float2*)&g_OT[((size_t)b*HID_ + j*NH + h)*L_ + k] = v;
            }
        }
    }
}

// =============================================================================
extern "C" void kernel_launch(void* const* d_in, const int* in_sizes, int n_in,
                              void* d_out, int out_size)
{
    const float* KEY   = (const float*)d_in[0];
    const float* VALUE = (const float*)d_in[1];
    const float* QUERY = (const float*)d_in[2];
    const float* W_w   = (const float*)d_in[3];
    const float* W_b   = (const float*)d_in[4];
    const float* Wv_w  = (const float*)d_in[5];
    const float* Wv_b  = (const float*)d_in[6];
    const float* Wo_w  = (const float*)d_in[7];
    const float* Wo_b  = (const float*)d_in[8];
    float* out = (float*)d_out;

    const int DYN = 4*64*136*2;   // 69632 bytes
    cudaFuncSetAttribute(score_softmax_kernel, cudaFuncAttributeMaxDynamicSharedMemorySize, DYN);
    cudaFuncSetAttribute(av_kernel,            cudaFuncAttributeMaxDynamicSharedMemorySize, DYN);

    dim3 blk(256);
    // projections (split-fp16, fp32-accurate) -> per-head fp16 layout
    gemm_split_kernel<<<dim3(8,64), blk>>>(KEY,   W_w,  W_b,  nullptr, MTOT, HID_, CIN, 0, 0);
    gemm_split_kernel<<<dim3(8,64), blk>>>(QUERY, W_w,  W_b,  nullptr, MTOT, HID_, CIN, 0, 1);
    gemm_split_kernel<<<dim3(8,64), blk>>>(VALUE, Wv_w, Wv_b, nullptr, MTOT, HID_, CIN, 0, 2);
    // scores for all heads + softmax over heads
    score_softmax_kernel<<<dim3(L_/64, L_/64, B_), blk, DYN>>>();
    // attn^T @ V per (b,h) -> O^T
    av_kernel<<<dim3(L_/128, NH, B_), blk, DYN>>>();
    // final projection (reads g_OT)
    gemm_split_kernel<<<dim3(2,64), blk>>>(nullptr, Wo_w, Wo_b, out, MTOT, OUT_, HID_, 1, 0);
}

// round 4
// speedup vs baseline: 1.5202x; 1.0818x over previous
#include <cuda_runtime.h>
#include <cuda_fp16.h>
#include <stdint.h>

#define B_   4
#define L_   2048
#define CIN  256
#define HID_ 1024
#define NH   8
#define HD   128
#define OUT_ 256
#define MTOT (B_*L_)   // 8192

// ---------------- scratch (device globals; no allocs allowed) ----------------
__device__ __align__(16) __half g_Pk [(size_t)B_*NH*L_*HD];    // [b,h][i][d]
__device__ __align__(16) __half g_Pq [(size_t)B_*NH*L_*HD];    // [b,h][k][d] (pre-scaled 1/sqrt(128))
__device__ __align__(16) __half g_PvT[(size_t)B_*NH*HD*L_];    // [b,h][j][i] (transposed V)
__device__ __align__(16) __half g_attn[(size_t)B_*NH*L_*L_];   // attnT: [b,h][k][i]
__device__ __align__(16) float  g_OT[(size_t)B_*HID_*L_];      // O^T: [b][j*8+h][k]

// ---------------- helpers ----------------
__device__ __forceinline__ uint32_t cvta_s(const void* p){
    return (uint32_t)__cvta_generic_to_shared(p);
}
__device__ __forceinline__ void ldm_x4(uint32_t* r, uint32_t a){
    asm volatile("ldmatrix.sync.aligned.m8n8.x4.shared.b16 {%0,%1,%2,%3},[%4];\n"
        :"=r"(r[0]),"=r"(r[1]),"=r"(r[2]),"=r"(r[3]):"r"(a));
}
__device__ __forceinline__ void mma_f16(float* d, const uint32_t* a, const uint32_t* b, const float* c){
    asm volatile("mma.sync.aligned.m16n8k16.row.col.f32.f16.f16.f32 "
        "{%0,%1,%2,%3},{%4,%5,%6,%7},{%8,%9},{%10,%11,%12,%13};\n"
        :"=f"(d[0]),"=f"(d[1]),"=f"(d[2]),"=f"(d[3])
        :"r"(a[0]),"r"(a[1]),"r"(a[2]),"r"(a[3]),"r"(b[0]),"r"(b[1]),
         "f"(c[0]),"f"(c[1]),"f"(c[2]),"f"(c[3]));
}
__device__ __forceinline__ void mma_f16h(uint32_t* d, const uint32_t* a, const uint32_t* b){
    asm volatile("mma.sync.aligned.m16n8k16.row.col.f16.f16.f16.f16 "
        "{%0,%1},{%2,%3,%4,%5},{%6,%7},{%8,%9};\n"
        :"=r"(d[0]),"=r"(d[1])
        :"r"(a[0]),"r"(a[1]),"r"(a[2]),"r"(a[3]),"r"(b[0]),"r"(b[1]),
         "r"(d[0]),"r"(d[1]));
}
__device__ __forceinline__ void cp16(void* dst_smem, const void* src){
    uint32_t d = cvta_s(dst_smem);
    asm volatile("cp.async.cg.shared.global [%0],[%1],16;\n"::"r"(d),"l"(src));
}
#define CP_COMMIT() asm volatile("cp.async.commit_group;\n")
#define CP_WAIT(n)  asm volatile("cp.async.wait_group %0;\n"::"n"(n))

__device__ __forceinline__ void split2h(float x, __half& hi, __half& lo){
    hi = __float2half_rn(x);
    lo = __float2half_rn(x - __half2float(hi));
}

// =============================================================================
// Kernel 1: split-fp16 TN GEMM  C[M,N] = A[M,K] @ W[N,K]^T + bias
//   mode 0: A from gmem fp32; write fp16 head layout (Q scaled; V transposed)
//   mode 1: A from g_OT (fp32 transposed); write fp32 C row-major
// =============================================================================
__global__ __launch_bounds__(256,1) void gemm_split_kernel(
    const float* __restrict__ A, const float* __restrict__ W,
    const float* __restrict__ bias, float* __restrict__ Cout,
    int M, int N, int K, int mode, int which)
{
    __shared__ __align__(16) __half Ah[128][40];
    __shared__ __align__(16) __half Al[128][40];
    __shared__ __align__(16) __half Bh[128][40];
    __shared__ __align__(16) __half Bl[128][40];

    const int tid  = threadIdx.x;
    const int lane = tid & 31, wid = tid >> 5;
    const int wm = wid >> 1, wn = wid & 1;
    const int m0 = blockIdx.y * 128, n0 = blockIdx.x * 128;

    float acc[2][8][4];
    #pragma unroll
    for (int i=0;i<2;i++){ for(int j=0;j<8;j++){ for(int e=0;e<4;e++) acc[i][j][e]=0.f; } }

    for (int kk=0; kk<K; kk+=32) {
        __syncthreads();
        if (mode==0){
            #pragma unroll
            for (int it=0; it<4; it++){
                int idx = tid + it*256;
                int r = idx >> 3, c = (idx & 7) * 4;
                float4 va = *(const float4*)(A + (size_t)(m0+r)*K + kk + c);
                __half h,l;
                split2h(va.x,h,l); Ah[r][c+0]=h; Al[r][c+0]=l;
                split2h(va.y,h,l); Ah[r][c+1]=h; Al[r][c+1]=l;
                split2h(va.z,h,l); Ah[r][c+2]=h; Al[r][c+2]=l;
                split2h(va.w,h,l); Ah[r][c+3]=h; Al[r][c+3]=l;
            }
        } else {
            int b  = m0 >> 11, l0 = m0 & 2047;
            #pragma unroll
            for (int it=0; it<4; it++){
                int idx = tid + it*256;
                int r = idx >> 5, c = (idx & 31) * 4;
                float4 va = *(const float4*)(g_OT + ((size_t)b*HID_ + kk + r)*L_ + l0 + c);
                __half h,l;
                split2h(va.x,h,l); Ah[c+0][r]=h; Al[c+0][r]=l;
                split2h(va.y,h,l); Ah[c+1][r]=h; Al[c+1][r]=l;
                split2h(va.z,h,l); Ah[c+2][r]=h; Al[c+2][r]=l;
                split2h(va.w,h,l); Ah[c+3][r]=h; Al[c+3][r]=l;
            }
        }
        #pragma unroll
        for (int it=0; it<4; it++){
            int idx = tid + it*256;
            int r = idx >> 3, c = (idx & 7) * 4;
            float4 vb = *(const float4*)(W + (size_t)(n0+r)*K + kk + c);
            __half h,l;
            split2h(vb.x*256.f,h,l); Bh[r][c+0]=h; Bl[r][c+0]=l;
            split2h(vb.y*256.f,h,l); Bh[r][c+1]=h; Bl[r][c+1]=l;
            split2h(vb.z*256.f,h,l); Bh[r][c+2]=h; Bl[r][c+2]=l;
            split2h(vb.w*256.f,h,l); Bh[r][c+3]=h; Bl[r][c+3]=l;
        }
        __syncthreads();
        #pragma unroll
        for (int ks=0; ks<2; ks++){
            uint32_t ah[2][4], al[2][4];
            #pragma unroll
            for (int mt=0; mt<2; mt++){
                ldm_x4(ah[mt], cvta_s(&Ah[wm*32+mt*16+(lane&15)][ks*16+(lane>>4)*8]));
                ldm_x4(al[mt], cvta_s(&Al[wm*32+mt*16+(lane&15)][ks*16+(lane>>4)*8]));
            }
            uint32_t bh[8][2], bl[8][2];
            #pragma unroll
            for (int p=0;p<4;p++){
                uint32_t r4[4];
                ldm_x4(r4, cvta_s(&Bh[wn*64+p*16+(lane&15)][ks*16+(lane>>4)*8]));
                bh[2*p][0]=r4[0]; bh[2*p][1]=r4[2]; bh[2*p+1][0]=r4[1]; bh[2*p+1][1]=r4[3];
                ldm_x4(r4, cvta_s(&Bl[wn*64+p*16+(lane&15)][ks*16+(lane>>4)*8]));
                bl[2*p][0]=r4[0]; bl[2*p][1]=r4[2]; bl[2*p+1][0]=r4[1]; bl[2*p+1][1]=r4[3];
            }
            #pragma unroll
            for (int mt=0; mt<2; mt++){
                #pragma unroll
                for (int nt=0; nt<8; nt++){
                    mma_f16(acc[mt][nt], ah[mt], bh[nt], acc[mt][nt]);
                    mma_f16(acc[mt][nt], ah[mt], bl[nt], acc[mt][nt]);
                    mma_f16(acc[mt][nt], al[mt], bh[nt], acc[mt][nt]);
                }
            }
        }
    }
    const float inv = 1.f/256.f;
    const float qs  = (which==1) ? 0.08838834764831845f : 1.0f;
    #pragma unroll
    for (int mt=0; mt<2; mt++){
        #pragma unroll
        for (int nt=0; nt<8; nt++){
            #pragma unroll
            for (int e=0; e<4; e++){
                int m = m0 + wm*32 + mt*16 + (lane>>2) + (e>>1)*8;
                int n = n0 + wn*64 + nt*8 + (lane&3)*2 + (e&1);
                float v = acc[mt][nt][e]*inv + bias[n];
                if (mode==0){
                    int b = m >> 11, l = m & 2047;
                    int h = n & 7,  d = n >> 3;
                    if (which==2){
                        g_PvT[(((size_t)(b*NH+h))*HD + d)*L_ + l] = __float2half_rn(v);
                    } else {
                        __half* P = (which==0)? g_Pk : g_Pq;
                        P[(((size_t)(b*NH+h))*L_ + l)*HD + d] = __float2half_rn(v*qs);
                    }
                } else {
                    Cout[(size_t)m*N + n] = v;
                }
            }
        }
    }
}

// =============================================================================
// Kernel 2: scores (fp16 acc) + softmax over heads -> attnT [k][i]
//   3-buffer depth-1 cp.async pipeline, ONE sync per head.
// =============================================================================
__global__ __launch_bounds__(256,2) void score_softmax_kernel()
{
    extern __shared__ __align__(16) __half s_dyn[];
    __half (*Ks)[64][136] = (__half(*)[64][136])(s_dyn);               // 3 bufs
    __half (*Qs)[64][136] = (__half(*)[64][136])(s_dyn + 3*64*136);    // 3 bufs

    const int b  = blockIdx.z;
    const int i0 = blockIdx.y * 64, k0 = blockIdx.x * 64;
    const int tid = threadIdx.x, lane = tid & 31, wid = tid >> 5;
    const int wi = wid >> 1, wk = wid & 1;     // wi: M(k-dim), wk: N(i-dim)

    uint32_t acc[NH][4][2];
    #pragma unroll
    for (int h=0;h<NH;h++){ for(int nt=0;nt<4;nt++){ acc[h][nt][0]=0u; acc[h][nt][1]=0u; } }

    const int lr = tid >> 4, lc = (tid & 15) * 8;

    #define SC_LOAD(hh) do {                                                  \
        int _buf = (hh)%3;                                                    \
        const __half* _Kp = g_Pk + (((size_t)(b*NH+(hh)))*L_ + i0)*HD;        \
        const __half* _Qp = g_Pq + (((size_t)(b*NH+(hh)))*L_ + k0)*HD;        \
        _Pragma("unroll")                                                     \
        for (int _it=0; _it<4; _it++){                                        \
            int _r = lr + _it*16;                                             \
            cp16(&Ks[_buf][_r][lc], _Kp + (size_t)_r*HD + lc);                \
            cp16(&Qs[_buf][_r][lc], _Qp + (size_t)_r*HD + lc);                \
        }                                                                     \
        CP_COMMIT();                                                          \
    } while(0)

    SC_LOAD(0);

    #pragma unroll
    for (int h=0; h<NH; h++){
        if (h < NH-1){ SC_LOAD(h+1); CP_WAIT(1); }
        else         { CP_WAIT(0); }
        __syncthreads();
        const int cb = h%3;
        #pragma unroll
        for (int ks=0; ks<8; ks++){
            uint32_t af[4];
            ldm_x4(af, cvta_s(&Qs[cb][wi*16+(lane&15)][ks*16+(lane>>4)*8]));   // M = k
            uint32_t bf[4][2];
            #pragma unroll
            for (int p=0;p<2;p++){
                uint32_t r4[4];
                ldm_x4(r4, cvta_s(&Ks[cb][wk*32+p*16+(lane&15)][ks*16+(lane>>4)*8])); // N = i
                bf[2*p][0]=r4[0]; bf[2*p][1]=r4[2]; bf[2*p+1][0]=r4[1]; bf[2*p+1][1]=r4[3];
            }
            #pragma unroll
            for (int nt=0; nt<4; nt++) mma_f16h(acc[h][nt], af, bf[nt]);
        }
    }
    #undef SC_LOAD

    // softmax over heads -> attnT[k][i]
    #pragma unroll
    for (int nt=0; nt<4; nt++){
        #pragma unroll
        for (int p=0; p<2; p++){
            float ex[NH][2]; float s0=0.f, s1=0.f;
            #pragma unroll
            for (int h=0;h<NH;h++){
                float2 f = __half22float2(*(__half2*)&acc[h][nt][p]);
                float e0 = __expf(f.x), e1 = __expf(f.y);
                ex[h][0]=e0; ex[h][1]=e1; s0+=e0; s1+=e1;
            }
            float r0 = 1.f/s0, r1 = 1.f/s1;
            int k = k0 + wi*16 + (lane>>2) + p*8;
            int i = i0 + wk*32 + nt*8 + (lane&3)*2;
            #pragma unroll
            for (int h=0;h<NH;h++){
                __half2 v = __floats2half2_rn(ex[h][0]*r0, ex[h][1]*r1);
                *(__half2*)&g_attn[(((size_t)(b*NH+h))*L_ + k)*L_ + i] = v;
            }
        }
    }
}

// =============================================================================
// Kernel 3: O^T[j][k] = sum_i PvT[j][i] * attnT[k][i]   (all non-trans ldmatrix)
//   CTA per (k0=128, h, b); warp tile 32j x 64k; 3-buffer depth-1 pipeline.
// =============================================================================
#define AV_NS (L_/64)
__global__ __launch_bounds__(256,2) void av_kernel()
{
    extern __shared__ __align__(16) __half s_dyn2[];
    __half (*As)[128][72] = (__half(*)[128][72])(s_dyn2);               // PvT tiles, 3 bufs
    __half (*Bs)[128][72] = (__half(*)[128][72])(s_dyn2 + 3*128*72);    // attnT tiles, 3 bufs

    const int b = blockIdx.z, h = blockIdx.y;
    const int k0 = blockIdx.x * 128;
    const int tid = threadIdx.x, lane = tid & 31, wid = tid >> 5;
    const int wj = wid >> 1, wk = wid & 1;     // warp tile 32(j) x 64(k)

    float acc[2][8][4];
    #pragma unroll
    for (int i=0;i<2;i++){ for(int j=0;j<8;j++){ for(int e=0;e<4;e++) acc[i][j][e]=0.f; } }

    const __half* At = g_attn + ((size_t)(b*NH+h))*L_*L_ + (size_t)k0*L_; // rows k, stride L_
    const __half* Vt = g_PvT  + ((size_t)(b*NH+h))*HD*L_;                 // rows j, stride L_

    const int lr = tid >> 3;              // 0..31 (row group)
    const int lc = (tid & 7) * 8;         // 0..56 (col, halfs)

    #define AV_LOAD(ss) do {                                                  \
        int _buf = (ss)%3; int _i0 = (ss)*64;                                 \
        _Pragma("unroll")                                                     \
        for (int _it=0; _it<4; _it++){                                        \
            int _r = lr + _it*32;                                             \
            cp16(&As[_buf][_r][lc], Vt + (size_t)_r*L_ + _i0 + lc);           \
            cp16(&Bs[_buf][_r][lc], At + (size_t)_r*L_ + _i0 + lc);           \
        }                                                                     \
        CP_COMMIT();                                                          \
    } while(0)

    AV_LOAD(0);

    for (int s=0; s<AV_NS; s++){
        if (s < AV_NS-1){ AV_LOAD(s+1); CP_WAIT(1); }
        else            { CP_WAIT(0); }
        __syncthreads();
        const int cb = s%3;
        #pragma unroll
        for (int ks=0; ks<4; ks++){
            uint32_t af[2][4];
            #pragma unroll
            for (int mt=0; mt<2; mt++)
                ldm_x4(af[mt], cvta_s(&As[cb][wj*32+mt*16+(lane&15)][ks*16+(lane>>4)*8]));
            uint32_t bf[8][2];
            #pragma unroll
            for (int p=0;p<4;p++){
                uint32_t r4[4];
                ldm_x4(r4, cvta_s(&Bs[cb][wk*64+p*16+(lane&15)][ks*16+(lane>>4)*8]));
                bf[2*p][0]=r4[0]; bf[2*p][1]=r4[2]; bf[2*p+1][0]=r4[1]; bf[2*p+1][1]=r4[3];
            }
            #pragma unroll
            for (int mt=0; mt<2; mt++){
                #pragma unroll
                for (int nt=0; nt<8; nt++)
                    mma_f16(acc[mt][nt], af[mt], bf[nt], acc[mt][nt]);
            }
        }
    }
    #undef AV_LOAD

    #pragma unroll
    for (int mt=0; mt<2; mt++){
        #pragma unroll
        for (int nt=0; nt<8; nt++){
            #pragma unroll
            for (int p=0; p<2; p++){
                int j = wj*32 + mt*16 + (lane>>2) + p*8;
                int k = k0 + wk*64 + nt*8 + (lane&3)*2;
                float2 v = make_float2(acc[mt][nt][p*2+0], acc[mt][nt][p*2+1]);
                *(float2*)&g_OT[((size_t)b*HID_ + j*NH + h)*L_ + k] = v;
            }
        }
    }
}

// =============================================================================
extern "C" void kernel_launch(void* const* d_in, const int* in_sizes, int n_in,
                              void* d_out, int out_size)
{
    const float* KEY   = (const float*)d_in[0];
    const float* VALUE = (const float*)d_in[1];
    const float* QUERY = (const float*)d_in[2];
    const float* W_w   = (const float*)d_in[3];
    const float* W_b   = (const float*)d_in[4];
    const float* Wv_w  = (const float*)d_in[5];
    const float* Wv_b  = (const float*)d_in[6];
    const float* Wo_w  = (const float*)d_in[7];
    const float* Wo_b  = (const float*)d_in[8];
    float* out = (float*)d_out;

    const int DYN_SC = 6*64*136*2;    // 104448 B (3 bufs x (K,Q))
    const int DYN_AV = 6*128*72*2;    // 110592 B (3 bufs x (A,B))
    cudaFuncSetAttribute(score_softmax_kernel, cudaFuncAttributeMaxDynamicSharedMemorySize, DYN_SC);
    cudaFuncSetAttribute(av_kernel,            cudaFuncAttributeMaxDynamicSharedMemorySize, DYN_AV);

    dim3 blk(256);
    gemm_split_kernel<<<dim3(8,64), blk>>>(KEY,   W_w,  W_b,  nullptr, MTOT, HID_, CIN, 0, 0);
    gemm_split_kernel<<<dim3(8,64), blk>>>(QUERY, W_w,  W_b,  nullptr, MTOT, HID_, CIN, 0, 1);
    gemm_split_kernel<<<dim3(8,64), blk>>>(VALUE, Wv_w, Wv_b, nullptr, MTOT, HID_, CIN, 0, 2);
    score_softmax_kernel<<<dim3(L_/64, L_/64, B_), blk, DYN_SC>>>();
    av_kernel<<<dim3(L_/128, NH, B_), blk, DYN_AV>>>();
    gemm_split_kernel<<<dim3(2,64), blk>>>(nullptr, Wo_w, Wo_b, out, MTOT, OUT_, HID_, 1, 0);
}

// round 5
// speedup vs baseline: 2.1866x; 1.4383x over previous
#include <cuda_runtime.h>
#include <cuda_fp16.h>
#include <stdint.h>

#define B_   4
#define L_   2048
#define CIN  256
#define HID_ 1024
#define NH   8
#define HD   128
#define OUT_ 256
#define MTOT (B_*L_)   // 8192

// ---------------- scratch (device globals; no allocs allowed) ----------------
__device__ __align__(16) __half g_K16[(size_t)MTOT*CIN];       // fp16 KEY
__device__ __align__(16) __half g_V16[(size_t)MTOT*CIN];       // fp16 VALUE
__device__ __align__(16) __half g_Q16[(size_t)MTOT*CIN];       // fp16 QUERY
__device__ __align__(16) __half g_Ww16[(size_t)HID_*CIN];
__device__ __align__(16) __half g_Wv16[(size_t)HID_*CIN];
__device__ __align__(16) __half g_Wo16[(size_t)OUT_*HID_];
__device__ __align__(16) __half g_Pk [(size_t)B_*NH*L_*HD];    // [b,h][i][d]
__device__ __align__(16) __half g_Pq [(size_t)B_*NH*L_*HD];    // [b,h][k][d] (pre-scaled 1/sqrt(128))
__device__ __align__(16) __half g_PvT[(size_t)B_*NH*HD*L_];    // [b,h][j][i]
__device__ __align__(16) __half g_attn[(size_t)B_*NH*L_*L_];   // attnT: [b,h][k][i]
__device__ __align__(16) __half g_OTh[(size_t)B_*HID_*L_];     // O^T fp16: [b][j*8+h][k]

// ---------------- helpers ----------------
__device__ __forceinline__ uint32_t cvta_s(const void* p){
    return (uint32_t)__cvta_generic_to_shared(p);
}
__device__ __forceinline__ void ldm_x4(uint32_t* r, uint32_t a){
    asm volatile("ldmatrix.sync.aligned.m8n8.x4.shared.b16 {%0,%1,%2,%3},[%4];\n"
        :"=r"(r[0]),"=r"(r[1]),"=r"(r[2]),"=r"(r[3]):"r"(a));
}
__device__ __forceinline__ void ldm_x4t(uint32_t* r, uint32_t a){
    asm volatile("ldmatrix.sync.aligned.m8n8.x4.trans.shared.b16 {%0,%1,%2,%3},[%4];\n"
        :"=r"(r[0]),"=r"(r[1]),"=r"(r[2]),"=r"(r[3]):"r"(a));
}
__device__ __forceinline__ void mma_f16(float* d, const uint32_t* a, const uint32_t* b, const float* c){
    asm volatile("mma.sync.aligned.m16n8k16.row.col.f32.f16.f16.f32 "
        "{%0,%1,%2,%3},{%4,%5,%6,%7},{%8,%9},{%10,%11,%12,%13};\n"
        :"=f"(d[0]),"=f"(d[1]),"=f"(d[2]),"=f"(d[3])
        :"r"(a[0]),"r"(a[1]),"r"(a[2]),"r"(a[3]),"r"(b[0]),"r"(b[1]),
         "f"(c[0]),"f"(c[1]),"f"(c[2]),"f"(c[3]));
}
__device__ __forceinline__ void mma_f16h(uint32_t* d, const uint32_t* a, const uint32_t* b){
    asm volatile("mma.sync.aligned.m16n8k16.row.col.f16.f16.f16.f16 "
        "{%0,%1},{%2,%3,%4,%5},{%6,%7},{%8,%9};\n"
        :"=r"(d[0]),"=r"(d[1])
        :"r"(a[0]),"r"(a[1]),"r"(a[2]),"r"(a[3]),"r"(b[0]),"r"(b[1]),
         "r"(d[0]),"r"(d[1]));
}
__device__ __forceinline__ void cp16(void* dst_smem, const void* src){
    uint32_t d = cvta_s(dst_smem);
    asm volatile("cp.async.cg.shared.global [%0],[%1],16;\n"::"r"(d),"l"(src));
}
#define CP_COMMIT() asm volatile("cp.async.commit_group;\n")
#define CP_WAIT(n)  asm volatile("cp.async.wait_group %0;\n"::"n"(n))

// =============================================================================
// Kernel 0: fp32 -> fp16 conversion (grid-stride over float4)
// =============================================================================
__global__ void cvt_kernel(const float* __restrict__ src, __half* __restrict__ dst, int n4)
{
    int i = blockIdx.x * blockDim.x + threadIdx.x;
    if (i < n4){
        float4 v = *(const float4*)(src + (size_t)i*4);
        __half2* d = (__half2*)(dst + (size_t)i*4);
        d[0] = __floats2half2_rn(v.x, v.y);
        d[1] = __floats2half2_rn(v.z, v.w);
    }
}

// =============================================================================
// Kernel 1: fp16 projection GEMM  C[M=8192, N=1024] = A @ W^T + bias
//   A, W fp16; fp32 accum; 128x128 tile; 3-buf depth-2 cp.async pipeline.
//   Epilogue: head-scatter fp16 (Q scaled by 1/sqrt(128); V transposed).
// =============================================================================
#define PR_NS (CIN/32)   // 8
__global__ __launch_bounds__(256,2) void proj_kernel(
    const __half* __restrict__ A16, const __half* __restrict__ W16,
    const float* __restrict__ bias, int which)
{
    extern __shared__ __align__(16) __half pr_s[];
    __half (*Ah)[128][40] = (__half(*)[128][40])(pr_s);                // 3 bufs
    __half (*Bh)[128][40] = (__half(*)[128][40])(pr_s + 3*128*40);     // 3 bufs

    const int tid  = threadIdx.x;
    const int lane = tid & 31, wid = tid >> 5;
    const int wm = wid >> 1, wn = wid & 1;          // warp tile 32m x 64n
    const int m0 = blockIdx.y * 128, n0 = blockIdx.x * 128;

    float acc[2][8][4];
    #pragma unroll
    for (int i=0;i<2;i++){ for(int j=0;j<8;j++){ for(int e=0;e<4;e++) acc[i][j][e]=0.f; } }

    const int lr = tid >> 2, lc = (tid & 3) * 8;    // 128 rows x 4 cp16

    #define PR_LOAD(ss) do {                                                 \
        int _buf = (ss)%3; int _kk = (ss)*32;                                \
        _Pragma("unroll")                                                    \
        for (int _t=0; _t<2; _t++){                                          \
            int _r = lr + _t*64;                                             \
            cp16(&Ah[_buf][_r][lc], A16 + (size_t)(m0+_r)*CIN + _kk + lc);   \
            cp16(&Bh[_buf][_r][lc], W16 + (size_t)(n0+_r)*CIN + _kk + lc);   \
        }                                                                    \
        CP_COMMIT();                                                         \
    } while(0)

    PR_LOAD(0); PR_LOAD(1);

    for (int s=0; s<PR_NS; s++){
        if (s < PR_NS-1) CP_WAIT(1); else CP_WAIT(0);
        __syncthreads();
        if (s+2 < PR_NS) PR_LOAD(s+2);
        const int cb = s%3;
        #pragma unroll
        for (int ks=0; ks<2; ks++){
            uint32_t af[2][4];
            #pragma unroll
            for (int mt=0; mt<2; mt++)
                ldm_x4(af[mt], cvta_s(&Ah[cb][wm*32+mt*16+(lane&15)][ks*16+(lane>>4)*8]));
            uint32_t bf[8][2];
            #pragma unroll
            for (int p=0;p<4;p++){
                uint32_t r4[4];
                ldm_x4(r4, cvta_s(&Bh[cb][wn*64+p*16+(lane&15)][ks*16+(lane>>4)*8]));
                bf[2*p][0]=r4[0]; bf[2*p][1]=r4[2]; bf[2*p+1][0]=r4[1]; bf[2*p+1][1]=r4[3];
            }
            #pragma unroll
            for (int mt=0; mt<2; mt++){
                #pragma unroll
                for (int nt=0; nt<8; nt++)
                    mma_f16(acc[mt][nt], af[mt], bf[nt], acc[mt][nt]);
            }
        }
        __syncthreads();
    }
    #undef PR_LOAD

    const float qs = (which==1) ? 0.08838834764831845f : 1.0f;
    #pragma unroll
    for (int mt=0; mt<2; mt++){
        #pragma unroll
        for (int nt=0; nt<8; nt++){
            #pragma unroll
            for (int e=0; e<4; e++){
                int m = m0 + wm*32 + mt*16 + (lane>>2) + (e>>1)*8;
                int n = n0 + wn*64 + nt*8 + (lane&3)*2 + (e&1);
                float v = acc[mt][nt][e] + bias[n];
                int b = m >> 11, l = m & 2047;
                int h = n & 7,  d = n >> 3;
                if (which==2){
                    g_PvT[(((size_t)(b*NH+h))*HD + d)*L_ + l] = __float2half_rn(v);
                } else {
                    __half* P = (which==0)? g_Pk : g_Pq;
                    P[(((size_t)(b*NH+h))*L_ + l)*HD + d] = __float2half_rn(v*qs);
                }
            }
        }
    }
}

// =============================================================================
// Kernel 2: scores (fp16 acc) + softmax over heads -> attnT [k][i]
//   3-buffer depth-2 cp.async pipeline over heads.
// =============================================================================
__global__ __launch_bounds__(256,2) void score_softmax_kernel()
{
    extern __shared__ __align__(16) __half s_dyn[];
    __half (*Ks)[64][136] = (__half(*)[64][136])(s_dyn);
    __half (*Qs)[64][136] = (__half(*)[64][136])(s_dyn + 3*64*136);

    const int b  = blockIdx.z;
    const int i0 = blockIdx.y * 64, k0 = blockIdx.x * 64;
    const int tid = threadIdx.x, lane = tid & 31, wid = tid >> 5;
    const int wi = wid >> 1, wk = wid & 1;     // wi: M(k-dim), wk: N(i-dim)

    uint32_t acc[NH][4][2];
    #pragma unroll
    for (int h=0;h<NH;h++){ for(int nt=0;nt<4;nt++){ acc[h][nt][0]=0u; acc[h][nt][1]=0u; } }

    const int lr = tid >> 4, lc = (tid & 15) * 8;

    #define SC_LOAD(hh) do {                                                  \
        int _buf = (hh)%3;                                                    \
        const __half* _Kp = g_Pk + (((size_t)(b*NH+(hh)))*L_ + i0)*HD;        \
        const __half* _Qp = g_Pq + (((size_t)(b*NH+(hh)))*L_ + k0)*HD;        \
        _Pragma("unroll")                                                     \
        for (int _it=0; _it<4; _it++){                                        \
            int _r = lr + _it*16;                                             \
            cp16(&Ks[_buf][_r][lc], _Kp + (size_t)_r*HD + lc);                \
            cp16(&Qs[_buf][_r][lc], _Qp + (size_t)_r*HD + lc);                \
        }                                                                     \
        CP_COMMIT();                                                          \
    } while(0)

    SC_LOAD(0); SC_LOAD(1);

    #pragma unroll
    for (int h=0; h<NH; h++){
        if (h < NH-1) CP_WAIT(1); else CP_WAIT(0);
        __syncthreads();
        if (h+2 < NH) SC_LOAD(h+2);
        const int cb = h%3;
        #pragma unroll
        for (int ks=0; ks<8; ks++){
            uint32_t af[4];
            ldm_x4(af, cvta_s(&Qs[cb][wi*16+(lane&15)][ks*16+(lane>>4)*8]));   // M = k
            uint32_t bf[4][2];
            #pragma unroll
            for (int p=0;p<2;p++){
                uint32_t r4[4];
                ldm_x4(r4, cvta_s(&Ks[cb][wk*32+p*16+(lane&15)][ks*16+(lane>>4)*8])); // N = i
                bf[2*p][0]=r4[0]; bf[2*p][1]=r4[2]; bf[2*p+1][0]=r4[1]; bf[2*p+1][1]=r4[3];
            }
            #pragma unroll
            for (int nt=0; nt<4; nt++) mma_f16h(acc[h][nt], af, bf[nt]);
        }
        __syncthreads();
    }
    #undef SC_LOAD

    // softmax over heads -> attnT[k][i]
    #pragma unroll
    for (int nt=0; nt<4; nt++){
        #pragma unroll
        for (int p=0; p<2; p++){
            float ex[NH][2]; float s0=0.f, s1=0.f;
            #pragma unroll
            for (int h=0;h<NH;h++){
                float2 f = __half22float2(*(__half2*)&acc[h][nt][p]);
                float e0 = __expf(f.x), e1 = __expf(f.y);
                ex[h][0]=e0; ex[h][1]=e1; s0+=e0; s1+=e1;
            }
            float r0 = 1.f/s0, r1 = 1.f/s1;
            int k = k0 + wi*16 + (lane>>2) + p*8;
            int i = i0 + wk*32 + nt*8 + (lane&3)*2;
            #pragma unroll
            for (int h=0;h<NH;h++){
                __half2 v = __floats2half2_rn(ex[h][0]*r0, ex[h][1]*r1);
                *(__half2*)&g_attn[(((size_t)(b*NH+h))*L_ + k)*L_ + i] = v;
            }
        }
    }
}

// =============================================================================
// Kernel 3: O^T[j][k] = sum_i PvT[j][i] * attnT[k][i]  -> fp16 g_OTh
//   CTA per (k0=128, h, b); warp tile 32j x 64k; 3-buf depth-2 pipeline.
// =============================================================================
#define AV_NS (L_/64)
__global__ __launch_bounds__(256,2) void av_kernel()
{
    extern __shared__ __align__(16) __half s_dyn2[];
    __half (*As)[128][72] = (__half(*)[128][72])(s_dyn2);               // PvT, 3 bufs
    __half (*Bs)[128][72] = (__half(*)[128][72])(s_dyn2 + 3*128*72);    // attnT, 3 bufs

    const int b = blockIdx.z, h = blockIdx.y;
    const int k0 = blockIdx.x * 128;
    const int tid = threadIdx.x, lane = tid & 31, wid = tid >> 5;
    const int wj = wid >> 1, wk = wid & 1;

    float acc[2][8][4];
    #pragma unroll
    for (int i=0;i<2;i++){ for(int j=0;j<8;j++){ for(int e=0;e<4;e++) acc[i][j][e]=0.f; } }

    const __half* At = g_attn + ((size_t)(b*NH+h))*L_*L_ + (size_t)k0*L_;
    const __half* Vt = g_PvT  + ((size_t)(b*NH+h))*HD*L_;

    const int lr = tid >> 3;
    const int lc = (tid & 7) * 8;

    #define AV_LOAD(ss) do {                                                  \
        int _buf = (ss)%3; int _i0 = (ss)*64;                                 \
        _Pragma("unroll")                                                     \
        for (int _it=0; _it<4; _it++){                                        \
            int _r = lr + _it*32;                                             \
            cp16(&As[_buf][_r][lc], Vt + (size_t)_r*L_ + _i0 + lc);           \
            cp16(&Bs[_buf][_r][lc], At + (size_t)_r*L_ + _i0 + lc);           \
        }                                                                     \
        CP_COMMIT();                                                          \
    } while(0)

    AV_LOAD(0); AV_LOAD(1);

    for (int s=0; s<AV_NS; s++){
        if (s < AV_NS-1) CP_WAIT(1); else CP_WAIT(0);
        __syncthreads();
        if (s+2 < AV_NS) AV_LOAD(s+2);
        const int cb = s%3;
        #pragma unroll
        for (int ks=0; ks<4; ks++){
            uint32_t af[2][4];
            #pragma unroll
            for (int mt=0; mt<2; mt++)
                ldm_x4(af[mt], cvta_s(&As[cb][wj*32+mt*16+(lane&15)][ks*16+(lane>>4)*8]));
            uint32_t bf[8][2];
            #pragma unroll
            for (int p=0;p<4;p++){
                uint32_t r4[4];
                ldm_x4(r4, cvta_s(&Bs[cb][wk*64+p*16+(lane&15)][ks*16+(lane>>4)*8]));
                bf[2*p][0]=r4[0]; bf[2*p][1]=r4[2]; bf[2*p+1][0]=r4[1]; bf[2*p+1][1]=r4[3];
            }
            #pragma unroll
            for (int mt=0; mt<2; mt++){
                #pragma unroll
                for (int nt=0; nt<8; nt++)
                    mma_f16(acc[mt][nt], af[mt], bf[nt], acc[mt][nt]);
            }
        }
        __syncthreads();
    }
    #undef AV_LOAD

    #pragma unroll
    for (int mt=0; mt<2; mt++){
        #pragma unroll
        for (int nt=0; nt<8; nt++){
            #pragma unroll
            for (int p=0; p<2; p++){
                int j = wj*32 + mt*16 + (lane>>2) + p*8;
                int k = k0 + wk*64 + nt*8 + (lane&3)*2;
                __half2 v = __floats2half2_rn(acc[mt][nt][p*2+0], acc[mt][nt][p*2+1]);
                *(__half2*)&g_OTh[((size_t)b*HID_ + j*NH + h)*L_ + k] = v;
            }
        }
    }
}

// =============================================================================
// Kernel 4: final GEMM  out[M=8192, N=256] = O @ Wo^T + bias
//   A = g_OTh fp16 [b][hid=k][l=m] (transposed) via trans-ldmatrix;
//   B = Wo fp16 [n][k]; 128x128 tile; 3-buf depth-2 pipeline; fp32 out.
// =============================================================================
#define FN_NS (HID_/32)  // 32
__global__ __launch_bounds__(256,2) void final_kernel(
    const float* __restrict__ bias, float* __restrict__ Cout)
{
    extern __shared__ __align__(16) __half fn_s[];
    __half (*At)[32][136] = (__half(*)[32][136])(fn_s);                 // 3 bufs (k x m)
    __half (*Bh)[128][40] = (__half(*)[128][40])(fn_s + 3*32*136);      // 3 bufs (n x k)

    const int tid  = threadIdx.x;
    const int lane = tid & 31, wid = tid >> 5;
    const int wm = wid >> 1, wn = wid & 1;
    const int m0 = blockIdx.y * 128, n0 = blockIdx.x * 128;
    const int b  = m0 >> 11, l0 = m0 & 2047;

    float acc[2][8][4];
    #pragma unroll
    for (int i=0;i<2;i++){ for(int j=0;j<8;j++){ for(int e=0;e<4;e++) acc[i][j][e]=0.f; } }

    const int ar = tid >> 4, ac = (tid & 15) * 8;   // A: 32 rows x 16 cp16
    const int br = tid >> 2, bc = (tid & 3) * 8;    // B: 128 rows x 4 cp16

    #define FN_LOAD(ss) do {                                                  \
        int _buf = (ss)%3; int _kk = (ss)*32;                                 \
        _Pragma("unroll")                                                     \
        for (int _t=0; _t<2; _t++){                                           \
            int _r = ar + _t*16;                                              \
            cp16(&At[_buf][_r][ac], g_OTh + ((size_t)b*HID_ + _kk + _r)*L_ + l0 + ac); \
        }                                                                     \
        _Pragma("unroll")                                                     \
        for (int _t=0; _t<2; _t++){                                           \
            int _r = br + _t*64;                                              \
            cp16(&Bh[_buf][_r][bc], g_Wo16 + (size_t)(n0+_r)*HID_ + _kk + bc); \
        }                                                                     \
        CP_COMMIT();                                                          \
    } while(0)

    FN_LOAD(0); FN_LOAD(1);

    for (int s=0; s<FN_NS; s++){
        if (s < FN_NS-1) CP_WAIT(1); else CP_WAIT(0);
        __syncthreads();
        if (s+2 < FN_NS) FN_LOAD(s+2);
        const int cb = s%3;
        #pragma unroll
        for (int ks=0; ks<2; ks++){
            uint32_t af[2][4];
            #pragma unroll
            for (int mt=0; mt<2; mt++)
                ldm_x4t(af[mt], cvta_s(
                    &At[cb][ks*16 + (lane&7) + ((lane>>4)&1)*8][wm*32 + mt*16 + ((lane>>3)&1)*8]));
            uint32_t bf[8][2];
            #pragma unroll
            for (int p=0;p<4;p++){
                uint32_t r4[4];
                ldm_x4(r4, cvta_s(&Bh[cb][wn*64+p*16+(lane&15)][ks*16+(lane>>4)*8]));
                bf[2*p][0]=r4[0]; bf[2*p][1]=r4[2]; bf[2*p+1][0]=r4[1]; bf[2*p+1][1]=r4[3];
            }
            #pragma unroll
            for (int mt=0; mt<2; mt++){
                #pragma unroll
                for (int nt=0; nt<8; nt++)
                    mma_f16(acc[mt][nt], af[mt], bf[nt], acc[mt][nt]);
            }
        }
        __syncthreads();
    }
    #undef FN_LOAD

    #pragma unroll
    for (int mt=0; mt<2; mt++){
        #pragma unroll
        for (int nt=0; nt<8; nt++){
            #pragma unroll
            for (int e=0; e<4; e++){
                int m = m0 + wm*32 + mt*16 + (lane>>2) + (e>>1)*8;
                int n = n0 + wn*64 + nt*8 + (lane&3)*2 + (e&1);
                Cout[(size_t)m*OUT_ + n] = acc[mt][nt][e] + bias[n];
            }
        }
    }
}

// =============================================================================
extern "C" void kernel_launch(void* const* d_in, const int* in_sizes, int n_in,
                              void* d_out, int out_size)
{
    const float* KEY   = (const float*)d_in[0];
    const float* VALUE = (const float*)d_in[1];
    const float* QUERY = (const float*)d_in[2];
    const float* W_w   = (const float*)d_in[3];
    const float* W_b   = (const float*)d_in[4];
    const float* Wv_w  = (const float*)d_in[5];
    const float* Wv_b  = (const float*)d_in[6];
    const float* Wo_w  = (const float*)d_in[7];
    const float* Wo_b  = (const float*)d_in[8];
    float* out = (float*)d_out;

    const int DYN_PR = 6*128*40*2;     // 61440
    const int DYN_SC = 6*64*136*2;     // 104448
    const int DYN_AV = 6*128*72*2;     // 110592
    const int DYN_FN = 3*32*136*2 + 3*128*40*2;  // 56832
    cudaFuncSetAttribute(proj_kernel,          cudaFuncAttributeMaxDynamicSharedMemorySize, DYN_PR);
    cudaFuncSetAttribute(score_softmax_kernel, cudaFuncAttributeMaxDynamicSharedMemorySize, DYN_SC);
    cudaFuncSetAttribute(av_kernel,            cudaFuncAttributeMaxDynamicSharedMemorySize, DYN_AV);
    cudaFuncSetAttribute(final_kernel,         cudaFuncAttributeMaxDynamicSharedMemorySize, DYN_FN);

    __half *p_K16, *p_V16, *p_Q16, *p_Ww16, *p_Wv16, *p_Wo16;
    cudaGetSymbolAddress((void**)&p_K16,  g_K16);
    cudaGetSymbolAddress((void**)&p_V16,  g_V16);
    cudaGetSymbolAddress((void**)&p_Q16,  g_Q16);
    cudaGetSymbolAddress((void**)&p_Ww16, g_Ww16);
    cudaGetSymbolAddress((void**)&p_Wv16, g_Wv16);
    cudaGetSymbolAddress((void**)&p_Wo16, g_Wo16);

    dim3 blk(256);
    // fp32 -> fp16 conversions
    cvt_kernel<<<MTOT*CIN/4/256, blk>>>(KEY,   p_K16,  MTOT*CIN/4);
    cvt_kernel<<<MTOT*CIN/4/256, blk>>>(VALUE, p_V16,  MTOT*CIN/4);
    cvt_kernel<<<MTOT*CIN/4/256, blk>>>(QUERY, p_Q16,  MTOT*CIN/4);
    cvt_kernel<<<HID_*CIN/4/256, blk>>>(W_w,   p_Ww16, HID_*CIN/4);
    cvt_kernel<<<HID_*CIN/4/256, blk>>>(Wv_w,  p_Wv16, HID_*CIN/4);
    cvt_kernel<<<OUT_*HID_/4/256, blk>>>(Wo_w, p_Wo16, OUT_*HID_/4);
    // projections
    proj_kernel<<<dim3(8,64), blk, DYN_PR>>>(p_K16, p_Ww16, W_b,  0);
    proj_kernel<<<dim3(8,64), blk, DYN_PR>>>(p_Q16, p_Ww16, W_b,  1);
    proj_kernel<<<dim3(8,64), blk, DYN_PR>>>(p_V16, p_Wv16, Wv_b, 2);
    // scores + head-softmax
    score_softmax_kernel<<<dim3(L_/64, L_/64, B_), blk, DYN_SC>>>();
    // attn^T @ V -> O^T fp16
    av_kernel<<<dim3(L_/128, NH, B_), blk, DYN_AV>>>();
    // final projection
    final_kernel<<<dim3(2,64), blk, DYN_FN>>>(Wo_b, out);
}

// round 6
// speedup vs baseline: 2.4035x; 1.0992x over previous
#include <cuda_runtime.h>
#include <cuda_fp16.h>
#include <stdint.h>

#define B_   4
#define L_   2048
#define CIN  256
#define HID_ 1024
#define NH   8
#define HD   128
#define OUT_ 256
#define MTOT (B_*L_)   // 8192

// ---------------- scratch (device globals; no allocs allowed) ----------------
__device__ __align__(16) __half g_K16[(size_t)MTOT*CIN];
__device__ __align__(16) __half g_V16[(size_t)MTOT*CIN];
__device__ __align__(16) __half g_Q16[(size_t)MTOT*CIN];
__device__ __align__(16) __half g_Ww16[(size_t)HID_*CIN];
__device__ __align__(16) __half g_Wv16[(size_t)HID_*CIN];
__device__ __align__(16) __half g_Wo16[(size_t)OUT_*HID_];
__device__ __align__(16) __half g_Pk [(size_t)B_*NH*L_*HD];    // [b,h][i][d]
__device__ __align__(16) __half g_Pq [(size_t)B_*NH*L_*HD];    // [b,h][k][d] (pre-scaled log2e/sqrt(128))
__device__ __align__(16) __half g_PvT[(size_t)B_*NH*HD*L_];    // [b,h][j][i]
__device__ __align__(16) __half g_attn[(size_t)B_*NH*L_*L_];   // attnT: [b,h][k][i]
__device__ __align__(16) __half g_OTh[(size_t)B_*HID_*L_];     // O^T fp16: [b][j*8+h][k]

// ---------------- helpers ----------------
__device__ __forceinline__ uint32_t cvta_s(const void* p){
    return (uint32_t)__cvta_generic_to_shared(p);
}
__device__ __forceinline__ void ldm_x4(uint32_t* r, uint32_t a){
    asm volatile("ldmatrix.sync.aligned.m8n8.x4.shared.b16 {%0,%1,%2,%3},[%4];\n"
        :"=r"(r[0]),"=r"(r[1]),"=r"(r[2]),"=r"(r[3]):"r"(a));
}
__device__ __forceinline__ void ldm_x4t(uint32_t* r, uint32_t a){
    asm volatile("ldmatrix.sync.aligned.m8n8.x4.trans.shared.b16 {%0,%1,%2,%3},[%4];\n"
        :"=r"(r[0]),"=r"(r[1]),"=r"(r[2]),"=r"(r[3]):"r"(a));
}
__device__ __forceinline__ void mma_f16(float* d, const uint32_t* a, const uint32_t* b, const float* c){
    asm volatile("mma.sync.aligned.m16n8k16.row.col.f32.f16.f16.f32 "
        "{%0,%1,%2,%3},{%4,%5,%6,%7},{%8,%9},{%10,%11,%12,%13};\n"
        :"=f"(d[0]),"=f"(d[1]),"=f"(d[2]),"=f"(d[3])
        :"r"(a[0]),"r"(a[1]),"r"(a[2]),"r"(a[3]),"r"(b[0]),"r"(b[1]),
         "f"(c[0]),"f"(c[1]),"f"(c[2]),"f"(c[3]));
}
__device__ __forceinline__ void mma_f16h(uint32_t* d, const uint32_t* a, const uint32_t* b){
    asm volatile("mma.sync.aligned.m16n8k16.row.col.f16.f16.f16.f16 "
        "{%0,%1},{%2,%3,%4,%5},{%6,%7},{%8,%9};\n"
        :"=r"(d[0]),"=r"(d[1])
        :"r"(a[0]),"r"(a[1]),"r"(a[2]),"r"(a[3]),"r"(b[0]),"r"(b[1]),
         "r"(d[0]),"r"(d[1]));
}
__device__ __forceinline__ void cp16(void* dst_smem, const void* src){
    uint32_t d = cvta_s(dst_smem);
    asm volatile("cp.async.cg.shared.global [%0],[%1],16;\n"::"r"(d),"l"(src));
}
#define CP_COMMIT() asm volatile("cp.async.commit_group;\n")
#define CP_WAIT(n)  asm volatile("cp.async.wait_group %0;\n"::"n"(n))

// =============================================================================
// Kernel 0: fp32 -> fp16, 3 equal-size segments per launch
// =============================================================================
__global__ void cvt3_kernel(const float* __restrict__ s0, __half* __restrict__ d0,
                            const float* __restrict__ s1, __half* __restrict__ d1,
                            const float* __restrict__ s2, __half* __restrict__ d2, int n4)
{
    const float* s = (blockIdx.y==0)? s0 : (blockIdx.y==1)? s1 : s2;
    __half*      d = (blockIdx.y==0)? d0 : (blockIdx.y==1)? d1 : d2;
    int i = blockIdx.x * blockDim.x + threadIdx.x;
    if (i < n4){
        float4 v = *(const float4*)(s + (size_t)i*4);
        __half2* o = (__half2*)(d + (size_t)i*4);
        o[0] = __floats2half2_rn(v.x, v.y);
        o[1] = __floats2half2_rn(v.z, v.w);
    }
}

// =============================================================================
// Kernel 1: fp16 projection GEMM  C[8192,1024] = A @ W^T + bias
// =============================================================================
#define PR_NS (CIN/32)   // 8
__global__ __launch_bounds__(256,2) void proj_kernel(
    const __half* __restrict__ A16, const __half* __restrict__ W16,
    const float* __restrict__ bias, int which)
{
    extern __shared__ __align__(16) __half pr_s[];
    __half (*Ah)[128][40] = (__half(*)[128][40])(pr_s);
    __half (*Bh)[128][40] = (__half(*)[128][40])(pr_s + 3*128*40);

    const int tid  = threadIdx.x;
    const int lane = tid & 31, wid = tid >> 5;
    const int wm = wid >> 1, wn = wid & 1;
    const int m0 = blockIdx.y * 128, n0 = blockIdx.x * 128;

    float acc[2][8][4];
    #pragma unroll
    for (int i=0;i<2;i++){ for(int j=0;j<8;j++){ for(int e=0;e<4;e++) acc[i][j][e]=0.f; } }

    const int lr = tid >> 2, lc = (tid & 3) * 8;

    #define PR_LOAD(ss) do {                                                 \
        int _buf = (ss)%3; int _kk = (ss)*32;                                \
        _Pragma("unroll")                                                    \
        for (int _t=0; _t<2; _t++){                                          \
            int _r = lr + _t*64;                                             \
            cp16(&Ah[_buf][_r][lc], A16 + (size_t)(m0+_r)*CIN + _kk + lc);   \
            cp16(&Bh[_buf][_r][lc], W16 + (size_t)(n0+_r)*CIN + _kk + lc);   \
        }                                                                    \
        CP_COMMIT();                                                         \
    } while(0)

    PR_LOAD(0); PR_LOAD(1);

    for (int s=0; s<PR_NS; s++){
        if (s < PR_NS-1) CP_WAIT(1); else CP_WAIT(0);
        __syncthreads();
        if (s+2 < PR_NS) PR_LOAD(s+2);
        const int cb = s%3;
        #pragma unroll
        for (int ks=0; ks<2; ks++){
            uint32_t af[2][4];
            #pragma unroll
            for (int mt=0; mt<2; mt++)
                ldm_x4(af[mt], cvta_s(&Ah[cb][wm*32+mt*16+(lane&15)][ks*16+(lane>>4)*8]));
            uint32_t bf[8][2];
            #pragma unroll
            for (int p=0;p<4;p++){
                uint32_t r4[4];
                ldm_x4(r4, cvta_s(&Bh[cb][wn*64+p*16+(lane&15)][ks*16+(lane>>4)*8]));
                bf[2*p][0]=r4[0]; bf[2*p][1]=r4[2]; bf[2*p+1][0]=r4[1]; bf[2*p+1][1]=r4[3];
            }
            #pragma unroll
            for (int mt=0; mt<2; mt++){
                #pragma unroll
                for (int nt=0; nt<8; nt++)
                    mma_f16(acc[mt][nt], af[mt], bf[nt], acc[mt][nt]);
            }
        }
    }
    #undef PR_LOAD

    // Q pre-scale: 1/sqrt(128) * log2(e)  (log2e folded for ex2-based softmax)
    const float qs = (which==1) ? (0.08838834764831845f * 1.4426950408889634f) : 1.0f;
    #pragma unroll
    for (int mt=0; mt<2; mt++){
        #pragma unroll
        for (int nt=0; nt<8; nt++){
            #pragma unroll
            for (int e=0; e<4; e++){
                int m = m0 + wm*32 + mt*16 + (lane>>2) + (e>>1)*8;
                int n = n0 + wn*64 + nt*8 + (lane&3)*2 + (e&1);
                float v = acc[mt][nt][e] + bias[n];
                int b = m >> 11, l = m & 2047;
                int h = n & 7,  d = n >> 3;
                if (which==2){
                    g_PvT[(((size_t)(b*NH+h))*HD + d)*L_ + l] = __float2half_rn(v);
                } else {
                    __half* P = (which==0)? g_Pk : g_Pq;
                    P[(((size_t)(b*NH+h))*L_ + l)*HD + d] = __float2half_rn(v*qs);
                }
            }
        }
    }
}

// =============================================================================
// Kernel 2: scores (fp16 acc) + packed-fp16 softmax over heads -> attnT [k][i]
//   acc holds score*log2e; softmax via h2exp2; smem-staged coalesced stores.
// =============================================================================
__global__ __launch_bounds__(256,2) void score_softmax_kernel()
{
    extern __shared__ __align__(16) __half s_dyn[];
    __half (*Ks)[64][136] = (__half(*)[64][136])(s_dyn);
    __half (*Qs)[64][136] = (__half(*)[64][136])(s_dyn + 3*64*136);
    __half (*attn_s)[64][72] = (__half(*)[64][72])(s_dyn);   // reused post-MMA: [8][64][72]

    const int b  = blockIdx.z;
    const int i0 = blockIdx.y * 64, k0 = blockIdx.x * 64;
    const int tid = threadIdx.x, lane = tid & 31, wid = tid >> 5;
    const int wi = wid >> 1, wk = wid & 1;     // wi: M(k-dim), wk: N(i-dim)

    uint32_t acc[NH][4][2];
    #pragma unroll
    for (int h=0;h<NH;h++){ for(int nt=0;nt<4;nt++){ acc[h][nt][0]=0u; acc[h][nt][1]=0u; } }

    const int lr = tid >> 4, lc = (tid & 15) * 8;

    #define SC_LOAD(hh) do {                                                  \
        int _buf = (hh)%3;                                                    \
        const __half* _Kp = g_Pk + (((size_t)(b*NH+(hh)))*L_ + i0)*HD;        \
        const __half* _Qp = g_Pq + (((size_t)(b*NH+(hh)))*L_ + k0)*HD;        \
        _Pragma("unroll")                                                     \
        for (int _it=0; _it<4; _it++){                                        \
            int _r = lr + _it*16;                                             \
            cp16(&Ks[_buf][_r][lc], _Kp + (size_t)_r*HD + lc);                \
            cp16(&Qs[_buf][_r][lc], _Qp + (size_t)_r*HD + lc);                \
        }                                                                     \
        CP_COMMIT();                                                          \
    } while(0)

    SC_LOAD(0); SC_LOAD(1);

    #pragma unroll
    for (int h=0; h<NH; h++){
        if (h < NH-1) CP_WAIT(1); else CP_WAIT(0);
        __syncthreads();
        if (h+2 < NH) SC_LOAD(h+2);
        const int cb = h%3;
        #pragma unroll
        for (int ks=0; ks<8; ks++){
            uint32_t af[4];
            ldm_x4(af, cvta_s(&Qs[cb][wi*16+(lane&15)][ks*16+(lane>>4)*8]));   // M = k
            uint32_t bf[4][2];
            #pragma unroll
            for (int p=0;p<2;p++){
                uint32_t r4[4];
                ldm_x4(r4, cvta_s(&Ks[cb][wk*32+p*16+(lane&15)][ks*16+(lane>>4)*8])); // N = i
                bf[2*p][0]=r4[0]; bf[2*p][1]=r4[2]; bf[2*p+1][0]=r4[1]; bf[2*p+1][1]=r4[3];
            }
            #pragma unroll
            for (int nt=0; nt<4; nt++) mma_f16h(acc[h][nt], af, bf[nt]);
        }
    }
    #undef SC_LOAD

    __syncthreads();   // done reading Ks/Qs: safe to reuse smem as attn_s

    // packed-fp16 softmax over heads: acc = score*log2e, weights = 2^acc / sum
    #pragma unroll
    for (int nt=0; nt<4; nt++){
        #pragma unroll
        for (int p=0; p<2; p++){
            __half2 e[NH];
            e[0] = h2exp2(*(__half2*)&acc[0][nt][p]);
            __half2 s = e[0];
            #pragma unroll
            for (int h=1;h<NH;h++){
                e[h] = h2exp2(*(__half2*)&acc[h][nt][p]);
                s = __hadd2(s, e[h]);
            }
            float2 sf = __half22float2(s);
            __half2 r = __floats2half2_rn(__fdividef(1.f, sf.x), __fdividef(1.f, sf.y));
            int kl = wi*16 + (lane>>2) + p*8;
            int il = wk*32 + nt*8 + (lane&3)*2;
            #pragma unroll
            for (int h=0;h<NH;h++)
                *(__half2*)&attn_s[h][kl][il] = __hmul2(e[h], r);
        }
    }
    __syncthreads();

    // coalesced copy-out: 8 x 64 rows of 128B
    #pragma unroll
    for (int t=0; t<16; t++){
        int idx = tid + t*256;            // 0..4095 uint4
        int row = idx >> 3, c = (idx & 7) * 8;
        int h = row >> 6,  k = row & 63;
        uint4 v = *(uint4*)&attn_s[h][k][c];
        *(uint4*)&g_attn[(((size_t)(b*NH+h))*L_ + k0 + k)*L_ + i0 + c] = v;
    }
}

// =============================================================================
// Kernel 3: O^T[j][k] = sum_i PvT[j][i] * attnT[k][i]  -> fp16 g_OTh
// =============================================================================
#define AV_NS (L_/64)
__global__ __launch_bounds__(256,2) void av_kernel()
{
    extern __shared__ __align__(16) __half s_dyn2[];
    __half (*As)[128][72] = (__half(*)[128][72])(s_dyn2);
    __half (*Bs)[128][72] = (__half(*)[128][72])(s_dyn2 + 3*128*72);

    const int b = blockIdx.z, h = blockIdx.y;
    const int k0 = blockIdx.x * 128;
    const int tid = threadIdx.x, lane = tid & 31, wid = tid >> 5;
    const int wj = wid >> 1, wk = wid & 1;

    float acc[2][8][4];
    #pragma unroll
    for (int i=0;i<2;i++){ for(int j=0;j<8;j++){ for(int e=0;e<4;e++) acc[i][j][e]=0.f; } }

    const __half* At = g_attn + ((size_t)(b*NH+h))*L_*L_ + (size_t)k0*L_;
    const __half* Vt = g_PvT  + ((size_t)(b*NH+h))*HD*L_;

    const int lr = tid >> 3;
    const int lc = (tid & 7) * 8;

    #define AV_LOAD(ss) do {                                                  \
        int _buf = (ss)%3; int _i0 = (ss)*64;                                 \
        _Pragma("unroll")                                                     \
        for (int _it=0; _it<4; _it++){                                        \
            int _r = lr + _it*32;                                             \
            cp16(&As[_buf][_r][lc], Vt + (size_t)_r*L_ + _i0 + lc);           \
            cp16(&Bs[_buf][_r][lc], At + (size_t)_r*L_ + _i0 + lc);           \
        }                                                                     \
        CP_COMMIT();                                                          \
    } while(0)

    AV_LOAD(0); AV_LOAD(1);

    for (int s=0; s<AV_NS; s++){
        if (s < AV_NS-1) CP_WAIT(1); else CP_WAIT(0);
        __syncthreads();
        if (s+2 < AV_NS) AV_LOAD(s+2);
        const int cb = s%3;
        #pragma unroll
        for (int ks=0; ks<4; ks++){
            uint32_t af[2][4];
            #pragma unroll
            for (int mt=0; mt<2; mt++)
                ldm_x4(af[mt], cvta_s(&As[cb][wj*32+mt*16+(lane&15)][ks*16+(lane>>4)*8]));
            uint32_t bf[8][2];
            #pragma unroll
            for (int p=0;p<4;p++){
                uint32_t r4[4];
                ldm_x4(r4, cvta_s(&Bs[cb][wk*64+p*16+(lane&15)][ks*16+(lane>>4)*8]));
                bf[2*p][0]=r4[0]; bf[2*p][1]=r4[2]; bf[2*p+1][0]=r4[1]; bf[2*p+1][1]=r4[3];
            }
            #pragma unroll
            for (int mt=0; mt<2; mt++){
                #pragma unroll
                for (int nt=0; nt<8; nt++)
                    mma_f16(acc[mt][nt], af[mt], bf[nt], acc[mt][nt]);
            }
        }
    }
    #undef AV_LOAD

    #pragma unroll
    for (int mt=0; mt<2; mt++){
        #pragma unroll
        for (int nt=0; nt<8; nt++){
            #pragma unroll
            for (int p=0; p<2; p++){
                int j = wj*32 + mt*16 + (lane>>2) + p*8;
                int k = k0 + wk*64 + nt*8 + (lane&3)*2;
                __half2 v = __floats2half2_rn(acc[mt][nt][p*2+0], acc[mt][nt][p*2+1]);
                *(__half2*)&g_OTh[((size_t)b*HID_ + j*NH + h)*L_ + k] = v;
            }
        }
    }
}

// =============================================================================
// Kernel 4: final GEMM  out[8192,256] = O @ Wo^T + bias  (A = g_OTh transposed)
// =============================================================================
#define FN_NS (HID_/32)  // 32
__global__ __launch_bounds__(256,2) void final_kernel(
    const float* __restrict__ bias, float* __restrict__ Cout)
{
    extern __shared__ __align__(16) __half fn_s[];
    __half (*At)[32][136] = (__half(*)[32][136])(fn_s);
    __half (*Bh)[128][40] = (__half(*)[128][40])(fn_s + 3*32*136);

    const int tid  = threadIdx.x;
    const int lane = tid & 31, wid = tid >> 5;
    const int wm = wid >> 1, wn = wid & 1;
    const int m0 = blockIdx.y * 128, n0 = blockIdx.x * 128;
    const int b  = m0 >> 11, l0 = m0 & 2047;

    float acc[2][8][4];
    #pragma unroll
    for (int i=0;i<2;i++){ for(int j=0;j<8;j++){ for(int e=0;e<4;e++) acc[i][j][e]=0.f; } }

    const int ar = tid >> 4, ac = (tid & 15) * 8;
    const int br = tid >> 2, bc = (tid & 3) * 8;

    #define FN_LOAD(ss) do {                                                  \
        int _buf = (ss)%3; int _kk = (ss)*32;                                 \
        _Pragma("unroll")                                                     \
        for (int _t=0; _t<2; _t++){                                           \
            int _r = ar + _t*16;                                              \
            cp16(&At[_buf][_r][ac], g_OTh + ((size_t)b*HID_ + _kk + _r)*L_ + l0 + ac); \
        }                                                                     \
        _Pragma("unroll")                                                     \
        for (int _t=0; _t<2; _t++){                                           \
            int _r = br + _t*64;                                              \
            cp16(&Bh[_buf][_r][bc], g_Wo16 + (size_t)(n0+_r)*HID_ + _kk + bc); \
        }                                                                     \
        CP_COMMIT();                                                          \
    } while(0)

    FN_LOAD(0); FN_LOAD(1);

    for (int s=0; s<FN_NS; s++){
        if (s < FN_NS-1) CP_WAIT(1); else CP_WAIT(0);
        __syncthreads();
        if (s+2 < FN_NS) FN_LOAD(s+2);
        const int cb = s%3;
        #pragma unroll
        for (int ks=0; ks<2; ks++){
            uint32_t af[2][4];
            #pragma unroll
            for (int mt=0; mt<2; mt++)
                ldm_x4t(af[mt], cvta_s(
                    &At[cb][ks*16 + (lane&7) + ((lane>>4)&1)*8][wm*32 + mt*16 + ((lane>>3)&1)*8]));
            uint32_t bf[8][2];
            #pragma unroll
            for (int p=0;p<4;p++){
                uint32_t r4[4];
                ldm_x4(r4, cvta_s(&Bh[cb][wn*64+p*16+(lane&15)][ks*16+(lane>>4)*8]));
                bf[2*p][0]=r4[0]; bf[2*p][1]=r4[2]; bf[2*p+1][0]=r4[1]; bf[2*p+1][1]=r4[3];
            }
            #pragma unroll
            for (int mt=0; mt<2; mt++){
                #pragma unroll
                for (int nt=0; nt<8; nt++)
                    mma_f16(acc[mt][nt], af[mt], bf[nt], acc[mt][nt]);
            }
        }
    }
    #undef FN_LOAD

    #pragma unroll
    for (int mt=0; mt<2; mt++){
        #pragma unroll
        for (int nt=0; nt<8; nt++){
            #pragma unroll
            for (int e=0; e<4; e++){
                int m = m0 + wm*32 + mt*16 + (lane>>2) + (e>>1)*8;
                int n = n0 + wn*64 + nt*8 + (lane&3)*2 + (e&1);
                Cout[(size_t)m*OUT_ + n] = acc[mt][nt][e] + bias[n];
            }
        }
    }
}

// =============================================================================
extern "C" void kernel_launch(void* const* d_in, const int* in_sizes, int n_in,
                              void* d_out, int out_size)
{
    const float* KEY   = (const float*)d_in[0];
    const float* VALUE = (const float*)d_in[1];
    const float* QUERY = (const float*)d_in[2];
    const float* W_w   = (const float*)d_in[3];
    const float* W_b   = (const float*)d_in[4];
    const float* Wv_w  = (const float*)d_in[5];
    const float* Wv_b  = (const float*)d_in[6];
    const float* Wo_w  = (const float*)d_in[7];
    const float* Wo_b  = (const float*)d_in[8];
    float* out = (float*)d_out;

    const int DYN_PR = 6*128*40*2;     // 61440
    const int DYN_SC = 6*64*136*2;     // 104448
    const int DYN_AV = 6*128*72*2;     // 110592
    const int DYN_FN = 3*32*136*2 + 3*128*40*2;  // 56832
    cudaFuncSetAttribute(proj_kernel,          cudaFuncAttributeMaxDynamicSharedMemorySize, DYN_PR);
    cudaFuncSetAttribute(score_softmax_kernel, cudaFuncAttributeMaxDynamicSharedMemorySize, DYN_SC);
    cudaFuncSetAttribute(av_kernel,            cudaFuncAttributeMaxDynamicSharedMemorySize, DYN_AV);
    cudaFuncSetAttribute(final_kernel,         cudaFuncAttributeMaxDynamicSharedMemorySize, DYN_FN);

    __half *p_K16, *p_V16, *p_Q16, *p_Ww16, *p_Wv16, *p_Wo16;
    cudaGetSymbolAddress((void**)&p_K16,  g_K16);
    cudaGetSymbolAddress((void**)&p_V16,  g_V16);
    cudaGetSymbolAddress((void**)&p_Q16,  g_Q16);
    cudaGetSymbolAddress((void**)&p_Ww16, g_Ww16);
    cudaGetSymbolAddress((void**)&p_Wv16, g_Wv16);
    cudaGetSymbolAddress((void**)&p_Wo16, g_Wo16);

    dim3 blk(256);
    // fp32 -> fp16: inputs (3 x 524288 float4), weights (3 x 65536 float4)
    cvt3_kernel<<<dim3(MTOT*CIN/4/256, 3), blk>>>(KEY, p_K16, VALUE, p_V16, QUERY, p_Q16, MTOT*CIN/4);
    cvt3_kernel<<<dim3(HID_*CIN/4/256, 3), blk>>>(W_w, p_Ww16, Wv_w, p_Wv16, Wo_w, p_Wo16, HID_*CIN/4);
    // projections
    proj_kernel<<<dim3(8,64), blk, DYN_PR>>>(p_K16, p_Ww16, W_b,  0);
    proj_kernel<<<dim3(8,64), blk, DYN_PR>>>(p_Q16, p_Ww16, W_b,  1);
    proj_kernel<<<dim3(8,64), blk, DYN_PR>>>(p_V16, p_Wv16, Wv_b, 2);
    // scores + head-softmax
    score_softmax_kernel<<<dim3(L_/64, L_/64, B_), blk, DYN_SC>>>();
    // attn^T @ V -> O^T fp16
    av_kernel<<<dim3(L_/128, NH, B_), blk, DYN_AV>>>();
    // final projection
    final_kernel<<<dim3(2,64), blk, DYN_FN>>>(Wo_b, out);
}

// round 7
// speedup vs baseline: 3.3007x; 1.3733x over previous
#include <cuda_runtime.h>
#include <cuda_fp16.h>
#include <stdint.h>

#define B_   4
#define L_   2048
#define CIN  256
#define HID_ 1024
#define NH   8
#define HD   128
#define OUT_ 256
#define MTOT (B_*L_)   // 8192

// ---------------- scratch (device globals; no allocs allowed) ----------------
__device__ __align__(16) __half g_K16[(size_t)MTOT*CIN];
__device__ __align__(16) __half g_V16[(size_t)MTOT*CIN];
__device__ __align__(16) __half g_Q16[(size_t)MTOT*CIN];
__device__ __align__(16) __half g_Ww16[(size_t)HID_*CIN];   // PERMUTED rows: p=(n&7)*128+(n>>3)
__device__ __align__(16) __half g_Wv16[(size_t)HID_*CIN];   // PERMUTED rows
__device__ __align__(16) __half g_Wo16[(size_t)OUT_*HID_];  // unpermuted
__device__ float g_Wb_p[HID_];                               // permuted biases
__device__ float g_Wvb_p[HID_];
__device__ __align__(16) __half g_Pk [(size_t)B_*NH*L_*HD];    // [b,h][i][d]
__device__ __align__(16) __half g_Pq [(size_t)B_*NH*L_*HD];    // [b,h][k][d] (pre-scaled log2e/sqrt(128))
__device__ __align__(16) __half g_PvT[(size_t)B_*NH*HD*L_];    // [b,h][j][i]
__device__ __align__(16) __half g_attn[(size_t)B_*NH*L_*L_];   // attnT: [b,h][k][i]
__device__ __align__(16) __half g_OTh[(size_t)B_*HID_*L_];     // O^T fp16: [b][j*8+h][k]

// ---------------- helpers ----------------
__device__ __forceinline__ uint32_t cvta_s(const void* p){
    return (uint32_t)__cvta_generic_to_shared(p);
}
__device__ __forceinline__ void ldm_x4(uint32_t* r, uint32_t a){
    asm volatile("ldmatrix.sync.aligned.m8n8.x4.shared.b16 {%0,%1,%2,%3},[%4];\n"
        :"=r"(r[0]),"=r"(r[1]),"=r"(r[2]),"=r"(r[3]):"r"(a));
}
__device__ __forceinline__ void ldm_x4t(uint32_t* r, uint32_t a){
    asm volatile("ldmatrix.sync.aligned.m8n8.x4.trans.shared.b16 {%0,%1,%2,%3},[%4];\n"
        :"=r"(r[0]),"=r"(r[1]),"=r"(r[2]),"=r"(r[3]):"r"(a));
}
__device__ __forceinline__ void mma_f16(float* d, const uint32_t* a, const uint32_t* b, const float* c){
    asm volatile("mma.sync.aligned.m16n8k16.row.col.f32.f16.f16.f32 "
        "{%0,%1,%2,%3},{%4,%5,%6,%7},{%8,%9},{%10,%11,%12,%13};\n"
        :"=f"(d[0]),"=f"(d[1]),"=f"(d[2]),"=f"(d[3])
        :"r"(a[0]),"r"(a[1]),"r"(a[2]),"r"(a[3]),"r"(b[0]),"r"(b[1]),
         "f"(c[0]),"f"(c[1]),"f"(c[2]),"f"(c[3]));
}
__device__ __forceinline__ void mma_f16h(uint32_t* d, const uint32_t* a, const uint32_t* b){
    asm volatile("mma.sync.aligned.m16n8k16.row.col.f16.f16.f16.f16 "
        "{%0,%1},{%2,%3,%4,%5},{%6,%7},{%8,%9};\n"
        :"=r"(d[0]),"=r"(d[1])
        :"r"(a[0]),"r"(a[1]),"r"(a[2]),"r"(a[3]),"r"(b[0]),"r"(b[1]),
         "r"(d[0]),"r"(d[1]));
}
__device__ __forceinline__ void cp16(void* dst_smem, const void* src){
    uint32_t d = cvta_s(dst_smem);
    asm volatile("cp.async.cg.shared.global [%0],[%1],16;\n"::"r"(d),"l"(src));
}
#define CP_COMMIT() asm volatile("cp.async.commit_group;\n")
#define CP_WAIT(n)  asm volatile("cp.async.wait_group %0;\n"::"n"(n))

// =============================================================================
// Kernel 0a: inputs fp32 -> fp16 (3 segments)
// =============================================================================
__global__ void cvt3_kernel(const float* __restrict__ s0,
                            const float* __restrict__ s1,
                            const float* __restrict__ s2, int n4)
{
    const float* s = (blockIdx.y==0)? s0 : (blockIdx.y==1)? s1 : s2;
    __half* d = (blockIdx.y==0)? g_K16 : (blockIdx.y==1)? g_V16 : g_Q16;
    int i = blockIdx.x * blockDim.x + threadIdx.x;
    if (i < n4){
        float4 v = *(const float4*)(s + (size_t)i*4);
        __half2* o = (__half2*)(d + (size_t)i*4);
        o[0] = __floats2half2_rn(v.x, v.y);
        o[1] = __floats2half2_rn(v.z, v.w);
    }
}

// =============================================================================
// Kernel 0b: weights fp32 -> fp16; W/Wv rows permuted p=(n&7)*128+(n>>3)
// =============================================================================
__global__ void cvtw_kernel(const float* __restrict__ Ww,
                            const float* __restrict__ Wv,
                            const float* __restrict__ Wo)
{
    int i = blockIdx.x * blockDim.x + threadIdx.x;    // float4 idx, 65536 per array
    if (blockIdx.y < 2){
        const float* s = blockIdx.y ? Wv : Ww;
        __half* d = blockIdx.y ? g_Wv16 : g_Ww16;
        int row = i >> 6, c4 = i & 63;                // CIN=256 -> 64 float4/row
        int pr = (row & 7)*128 + (row >> 3);
        float4 v = *(const float4*)(s + (size_t)i*4);
        __half2* o = (__half2*)(d + ((size_t)pr*CIN) + c4*4);
        o[0] = __floats2half2_rn(v.x, v.y);
        o[1] = __floats2half2_rn(v.z, v.w);
    } else {
        float4 v = *(const float4*)(Wo + (size_t)i*4);
        __half2* o = (__half2*)(g_Wo16 + (size_t)i*4);
        o[0] = __floats2half2_rn(v.x, v.y);
        o[1] = __floats2half2_rn(v.z, v.w);
    }
}

// Kernel 0c: permute biases
__global__ void bias_perm_kernel(const float* __restrict__ wb, const float* __restrict__ wvb)
{
    int n = blockIdx.x * 256 + threadIdx.x;           // 1024 total
    int p = (n & 7)*128 + (n >> 3);
    g_Wb_p[p]  = wb[n];
    g_Wvb_p[p] = wvb[n];
}

// =============================================================================
// Kernel 1: fp16 projection GEMM (merged K/Q/V via blockIdx.z)
//   Permuted weights => each n-tile of 128 = ONE head, d contiguous.
//   Epilogue: smem-staged, fully coalesced 256B-row stores.
// =============================================================================
#define PR_NS (CIN/32)   // 8
__global__ __launch_bounds__(256,2) void proj_kernel()
{
    extern __shared__ __align__(16) __half pr_s[];
    __half (*Ah)[128][40] = (__half(*)[128][40])(pr_s);
    __half (*Bh)[128][40] = (__half(*)[128][40])(pr_s + 3*128*40);
    __half (*stage)[136]  = (__half(*)[136])(pr_s);   // reused post-MMA: 128x136

    const int which = blockIdx.z;                     // 0=K, 1=Q, 2=V
    const __half* A16 = (which==0)? g_K16 : (which==1)? g_Q16 : g_V16;
    const __half* W16 = (which==2)? g_Wv16 : g_Ww16;
    const float*  bias= (which==2)? g_Wvb_p : g_Wb_p;

    const int tid  = threadIdx.x;
    const int lane = tid & 31, wid = tid >> 5;
    const int wm = wid >> 1, wn = wid & 1;
    const int m0 = blockIdx.y * 128, n0 = blockIdx.x * 128;

    float acc[2][8][4];
    #pragma unroll
    for (int i=0;i<2;i++){ for(int j=0;j<8;j++){ for(int e=0;e<4;e++) acc[i][j][e]=0.f; } }

    const int lr = tid >> 2, lc = (tid & 3) * 8;

    #define PR_LOAD(ss) do {                                                 \
        int _buf = (ss)%3; int _kk = (ss)*32;                                \
        _Pragma("unroll")                                                    \
        for (int _t=0; _t<2; _t++){                                          \
            int _r = lr + _t*64;                                             \
            cp16(&Ah[_buf][_r][lc], A16 + (size_t)(m0+_r)*CIN + _kk + lc);   \
            cp16(&Bh[_buf][_r][lc], W16 + (size_t)(n0+_r)*CIN + _kk + lc);   \
        }                                                                    \
        CP_COMMIT();                                                         \
    } while(0)

    PR_LOAD(0); PR_LOAD(1);

    for (int s=0; s<PR_NS; s++){
        if (s < PR_NS-1) CP_WAIT(1); else CP_WAIT(0);
        __syncthreads();
        if (s+2 < PR_NS) PR_LOAD(s+2);
        const int cb = s%3;
        #pragma unroll
        for (int ks=0; ks<2; ks++){
            uint32_t af[2][4];
            #pragma unroll
            for (int mt=0; mt<2; mt++)
                ldm_x4(af[mt], cvta_s(&Ah[cb][wm*32+mt*16+(lane&15)][ks*16+(lane>>4)*8]));
            uint32_t bf[8][2];
            #pragma unroll
            for (int p=0;p<4;p++){
                uint32_t r4[4];
                ldm_x4(r4, cvta_s(&Bh[cb][wn*64+p*16+(lane&15)][ks*16+(lane>>4)*8]));
                bf[2*p][0]=r4[0]; bf[2*p][1]=r4[2]; bf[2*p+1][0]=r4[1]; bf[2*p+1][1]=r4[3];
            }
            #pragma unroll
            for (int mt=0; mt<2; mt++){
                #pragma unroll
                for (int nt=0; nt<8; nt++)
                    mma_f16(acc[mt][nt], af[mt], bf[nt], acc[mt][nt]);
            }
        }
    }
    #undef PR_LOAD

    __syncthreads();   // all warps done with pipeline bufs -> reuse as stage

    // Q pre-scale: 1/sqrt(128) * log2(e)
    const float qs = (which==1) ? (0.08838834764831845f * 1.4426950408889634f) : 1.0f;
    const int hh = n0 >> 7;                 // one head per CTA
    const int b  = m0 >> 11, l0 = m0 & 2047;

    if (which==2){
        // stage TRANSPOSED: stage[d][l]
        #pragma unroll
        for (int mt=0; mt<2; mt++){
            #pragma unroll
            for (int nt=0; nt<8; nt++){
                #pragma unroll
                for (int e=0; e<4; e++){
                    int l = wm*32 + mt*16 + (lane>>2) + (e>>1)*8;
                    int d = wn*64 + nt*8 + (lane&3)*2 + (e&1);
                    stage[d][l] = __float2half_rn(acc[mt][nt][e] + bias[n0+d]);
                }
            }
        }
    } else {
        // stage normal: stage[l][d], paired stores
        #pragma unroll
        for (int mt=0; mt<2; mt++){
            #pragma unroll
            for (int nt=0; nt<8; nt++){
                #pragma unroll
                for (int p=0; p<2; p++){
                    int l = wm*32 + mt*16 + (lane>>2) + p*8;
                    int d = wn*64 + nt*8 + (lane&3)*2;
                    __half2 v = __floats2half2_rn(
                        (acc[mt][nt][p*2+0] + bias[n0+d])   * qs,
                        (acc[mt][nt][p*2+1] + bias[n0+d+1]) * qs);
                    *(__half2*)&stage[l][d] = v;
                }
            }
        }
    }
    __syncthreads();

    // coalesced copy-out: 128 rows x 256B
    #pragma unroll
    for (int t=0; t<8; t++){
        int idx = tid + t*256;                 // 2048 uint4
        int r = idx >> 4, c = (idx & 15) * 8;
        uint4 v = *(uint4*)&stage[r][c];
        if (which==2){
            *(uint4*)&g_PvT[((size_t)(b*NH+hh)*HD + r)*L_ + l0 + c] = v;
        } else {
            __half* P = which ? g_Pq : g_Pk;
            *(uint4*)&P[((size_t)(b*NH+hh)*L_ + l0 + r)*HD + c] = v;
        }
    }
}

// =============================================================================
// Kernel 2: scores (fp16 acc) + packed-fp16 softmax over heads -> attnT [k][i]
// =============================================================================
__global__ __launch_bounds__(256,2) void score_softmax_kernel()
{
    extern __shared__ __align__(16) __half s_dyn[];
    __half (*Ks)[64][136] = (__half(*)[64][136])(s_dyn);
    __half (*Qs)[64][136] = (__half(*)[64][136])(s_dyn + 3*64*136);
    __half (*attn_s)[64][72] = (__half(*)[64][72])(s_dyn);   // reused post-MMA

    const int b  = blockIdx.z;
    const int i0 = blockIdx.y * 64, k0 = blockIdx.x * 64;
    const int tid = threadIdx.x, lane = tid & 31, wid = tid >> 5;
    const int wi = wid >> 1, wk = wid & 1;

    uint32_t acc[NH][4][2];
    #pragma unroll
    for (int h=0;h<NH;h++){ for(int nt=0;nt<4;nt++){ acc[h][nt][0]=0u; acc[h][nt][1]=0u; } }

    const int lr = tid >> 4, lc = (tid & 15) * 8;

    #define SC_LOAD(hh) do {                                                  \
        int _buf = (hh)%3;                                                    \
        const __half* _Kp = g_Pk + (((size_t)(b*NH+(hh)))*L_ + i0)*HD;        \
        const __half* _Qp = g_Pq + (((size_t)(b*NH+(hh)))*L_ + k0)*HD;        \
        _Pragma("unroll")                                                     \
        for (int _it=0; _it<4; _it++){                                        \
            int _r = lr + _it*16;                                             \
            cp16(&Ks[_buf][_r][lc], _Kp + (size_t)_r*HD + lc);                \
            cp16(&Qs[_buf][_r][lc], _Qp + (size_t)_r*HD + lc);                \
        }                                                                     \
        CP_COMMIT();                                                          \
    } while(0)

    SC_LOAD(0); SC_LOAD(1);

    #pragma unroll
    for (int h=0; h<NH; h++){
        if (h < NH-1) CP_WAIT(1); else CP_WAIT(0);
        __syncthreads();
        if (h+2 < NH) SC_LOAD(h+2);
        const int cb = h%3;
        #pragma unroll
        for (int ks=0; ks<8; ks++){
            uint32_t af[4];
            ldm_x4(af, cvta_s(&Qs[cb][wi*16+(lane&15)][ks*16+(lane>>4)*8]));
            uint32_t bf[4][2];
            #pragma unroll
            for (int p=0;p<2;p++){
                uint32_t r4[4];
                ldm_x4(r4, cvta_s(&Ks[cb][wk*32+p*16+(lane&15)][ks*16+(lane>>4)*8]));
                bf[2*p][0]=r4[0]; bf[2*p][1]=r4[2]; bf[2*p+1][0]=r4[1]; bf[2*p+1][1]=r4[3];
            }
            #pragma unroll
            for (int nt=0; nt<4; nt++) mma_f16h(acc[h][nt], af, bf[nt]);
        }
    }
    #undef SC_LOAD

    __syncthreads();

    #pragma unroll
    for (int nt=0; nt<4; nt++){
        #pragma unroll
        for (int p=0; p<2; p++){
            __half2 e[NH];
            e[0] = h2exp2(*(__half2*)&acc[0][nt][p]);
            __half2 s = e[0];
            #pragma unroll
            for (int h=1;h<NH;h++){
                e[h] = h2exp2(*(__half2*)&acc[h][nt][p]);
                s = __hadd2(s, e[h]);
            }
            float2 sf = __half22float2(s);
            __half2 r = __floats2half2_rn(__fdividef(1.f, sf.x), __fdividef(1.f, sf.y));
            int kl = wi*16 + (lane>>2) + p*8;
            int il = wk*32 + nt*8 + (lane&3)*2;
            #pragma unroll
            for (int h=0;h<NH;h++)
                *(__half2*)&attn_s[h][kl][il] = __hmul2(e[h], r);
        }
    }
    __syncthreads();

    #pragma unroll
    for (int t=0; t<16; t++){
        int idx = tid + t*256;
        int row = idx >> 3, c = (idx & 7) * 8;
        int h = row >> 6,  k = row & 63;
        uint4 v = *(uint4*)&attn_s[h][k][c];
        *(uint4*)&g_attn[(((size_t)(b*NH+h))*L_ + k0 + k)*L_ + i0 + c] = v;
    }
}

// =============================================================================
// Kernel 3: O^T[j][k] = sum_i PvT[j][i] * attnT[k][i]  -> fp16 g_OTh
// =============================================================================
#define AV_NS (L_/64)
__global__ __launch_bounds__(256,2) void av_kernel()
{
    extern __shared__ __align__(16) __half s_dyn2[];
    __half (*As)[128][72] = (__half(*)[128][72])(s_dyn2);
    __half (*Bs)[128][72] = (__half(*)[128][72])(s_dyn2 + 3*128*72);

    const int b = blockIdx.z, h = blockIdx.y;
    const int k0 = blockIdx.x * 128;
    const int tid = threadIdx.x, lane = tid & 31, wid = tid >> 5;
    const int wj = wid >> 1, wk = wid & 1;

    float acc[2][8][4];
    #pragma unroll
    for (int i=0;i<2;i++){ for(int j=0;j<8;j++){ for(int e=0;e<4;e++) acc[i][j][e]=0.f; } }

    const __half* At = g_attn + ((size_t)(b*NH+h))*L_*L_ + (size_t)k0*L_;
    const __half* Vt = g_PvT  + ((size_t)(b*NH+h))*HD*L_;

    const int lr = tid >> 3;
    const int lc = (tid & 7) * 8;

    #define AV_LOAD(ss) do {                                                  \
        int _buf = (ss)%3; int _i0 = (ss)*64;                                 \
        _Pragma("unroll")                                                     \
        for (int _it=0; _it<4; _it++){                                        \
            int _r = lr + _it*32;                                             \
            cp16(&As[_buf][_r][lc], Vt + (size_t)_r*L_ + _i0 + lc);           \
            cp16(&Bs[_buf][_r][lc], At + (size_t)_r*L_ + _i0 + lc);           \
        }                                                                     \
        CP_COMMIT();                                                          \
    } while(0)

    AV_LOAD(0); AV_LOAD(1);

    for (int s=0; s<AV_NS; s++){
        if (s < AV_NS-1) CP_WAIT(1); else CP_WAIT(0);
        __syncthreads();
        if (s+2 < AV_NS) AV_LOAD(s+2);
        const int cb = s%3;
        #pragma unroll
        for (int ks=0; ks<4; ks++){
            uint32_t af[2][4];
            #pragma unroll
            for (int mt=0; mt<2; mt++)
                ldm_x4(af[mt], cvta_s(&As[cb][wj*32+mt*16+(lane&15)][ks*16+(lane>>4)*8]));
            uint32_t bf[8][2];
            #pragma unroll
            for (int p=0;p<4;p++){
                uint32_t r4[4];
                ldm_x4(r4, cvta_s(&Bs[cb][wk*64+p*16+(lane&15)][ks*16+(lane>>4)*8]));
                bf[2*p][0]=r4[0]; bf[2*p][1]=r4[2]; bf[2*p+1][0]=r4[1]; bf[2*p+1][1]=r4[3];
            }
            #pragma unroll
            for (int mt=0; mt<2; mt++){
                #pragma unroll
                for (int nt=0; nt<8; nt++)
                    mma_f16(acc[mt][nt], af[mt], bf[nt], acc[mt][nt]);
            }
        }
    }
    #undef AV_LOAD

    #pragma unroll
    for (int mt=0; mt<2; mt++){
        #pragma unroll
        for (int nt=0; nt<8; nt++){
            #pragma unroll
            for (int p=0; p<2; p++){
                int j = wj*32 + mt*16 + (lane>>2) + p*8;
                int k = k0 + wk*64 + nt*8 + (lane&3)*2;
                __half2 v = __floats2half2_rn(acc[mt][nt][p*2+0], acc[mt][nt][p*2+1]);
                *(__half2*)&g_OTh[((size_t)b*HID_ + j*NH + h)*L_ + k] = v;
            }
        }
    }
}

// =============================================================================
// Kernel 4: final GEMM  out[8192,256] = O @ Wo^T + bias  (A = g_OTh transposed)
// =============================================================================
#define FN_NS (HID_/32)  // 32
__global__ __launch_bounds__(256,2) void final_kernel(
    const float* __restrict__ bias, float* __restrict__ Cout)
{
    extern __shared__ __align__(16) __half fn_s[];
    __half (*At)[32][136] = (__half(*)[32][136])(fn_s);
    __half (*Bh)[128][40] = (__half(*)[128][40])(fn_s + 3*32*136);

    const int tid  = threadIdx.x;
    const int lane = tid & 31, wid = tid >> 5;
    const int wm = wid >> 1, wn = wid & 1;
    const int m0 = blockIdx.y * 128, n0 = blockIdx.x * 128;
    const int b  = m0 >> 11, l0 = m0 & 2047;

    float acc[2][8][4];
    #pragma unroll
    for (int i=0;i<2;i++){ for(int j=0;j<8;j++){ for(int e=0;e<4;e++) acc[i][j][e]=0.f; } }

    const int ar = tid >> 4, ac = (tid & 15) * 8;
    const int br = tid >> 2, bc = (tid & 3) * 8;

    #define FN_LOAD(ss) do {                                                  \
        int _buf = (ss)%3; int _kk = (ss)*32;                                 \
        _Pragma("unroll")                                                     \
        for (int _t=0; _t<2; _t++){                                           \
            int _r = ar + _t*16;                                              \
            cp16(&At[_buf][_r][ac], g_OTh + ((size_t)b*HID_ + _kk + _r)*L_ + l0 + ac); \
        }                                                                     \
        _Pragma("unroll")                                                     \
        for (int _t=0; _t<2; _t++){                                           \
            int _r = br + _t*64;                                              \
            cp16(&Bh[_buf][_r][bc], g_Wo16 + (size_t)(n0+_r)*HID_ + _kk + bc); \
        }                                                                     \
        CP_COMMIT();                                                          \
    } while(0)

    FN_LOAD(0); FN_LOAD(1);

    for (int s=0; s<FN_NS; s++){
        if (s < FN_NS-1) CP_WAIT(1); else CP_WAIT(0);
        __syncthreads();
        if (s+2 < FN_NS) FN_LOAD(s+2);
        const int cb = s%3;
        #pragma unroll
        for (int ks=0; ks<2; ks++){
            uint32_t af[2][4];
            #pragma unroll
            for (int mt=0; mt<2; mt++)
                ldm_x4t(af[mt], cvta_s(
                    &At[cb][ks*16 + (lane&7) + ((lane>>4)&1)*8][wm*32 + mt*16 + ((lane>>3)&1)*8]));
            uint32_t bf[8][2];
            #pragma unroll
            for (int p=0;p<4;p++){
                uint32_t r4[4];
                ldm_x4(r4, cvta_s(&Bh[cb][wn*64+p*16+(lane&15)][ks*16+(lane>>4)*8]));
                bf[2*p][0]=r4[0]; bf[2*p][1]=r4[2]; bf[2*p+1][0]=r4[1]; bf[2*p+1][1]=r4[3];
            }
            #pragma unroll
            for (int mt=0; mt<2; mt++){
                #pragma unroll
                for (int nt=0; nt<8; nt++)
                    mma_f16(acc[mt][nt], af[mt], bf[nt], acc[mt][nt]);
            }
        }
    }
    #undef FN_LOAD

    #pragma unroll
    for (int mt=0; mt<2; mt++){
        #pragma unroll
        for (int nt=0; nt<8; nt++){
            #pragma unroll
            for (int e=0; e<4; e++){
                int m = m0 + wm*32 + mt*16 + (lane>>2) + (e>>1)*8;
                int n = n0 + wn*64 + nt*8 + (lane&3)*2 + (e&1);
                Cout[(size_t)m*OUT_ + n] = acc[mt][nt][e] + bias[n];
            }
        }
    }
}

// =============================================================================
extern "C" void kernel_launch(void* const* d_in, const int* in_sizes, int n_in,
                              void* d_out, int out_size)
{
    const float* KEY   = (const float*)d_in[0];
    const float* VALUE = (const float*)d_in[1];
    const float* QUERY = (const float*)d_in[2];
    const float* W_w   = (const float*)d_in[3];
    const float* W_b   = (const float*)d_in[4];
    const float* Wv_w  = (const float*)d_in[5];
    const float* Wv_b  = (const float*)d_in[6];
    const float* Wo_w  = (const float*)d_in[7];
    const float* Wo_b  = (const float*)d_in[8];
    float* out = (float*)d_out;

    const int DYN_PR = 6*128*40*2;               // 61440
    const int DYN_SC = 6*64*136*2;               // 104448
    const int DYN_AV = 6*128*72*2;               // 110592
    const int DYN_FN = 3*32*136*2 + 3*128*40*2;  // 56832
    cudaFuncSetAttribute(proj_kernel,          cudaFuncAttributeMaxDynamicSharedMemorySize, DYN_PR);
    cudaFuncSetAttribute(score_softmax_kernel, cudaFuncAttributeMaxDynamicSharedMemorySize, DYN_SC);
    cudaFuncSetAttribute(av_kernel,            cudaFuncAttributeMaxDynamicSharedMemorySize, DYN_AV);
    cudaFuncSetAttribute(final_kernel,         cudaFuncAttributeMaxDynamicSharedMemorySize, DYN_FN);

    dim3 blk(256);
    // conversions (+ weight/bias permutation)
    cvt3_kernel<<<dim3(MTOT*CIN/4/256, 3), blk>>>(KEY, VALUE, QUERY, MTOT*CIN/4);
    cvtw_kernel<<<dim3(HID_*CIN/4/256, 3), blk>>>(W_w, Wv_w, Wo_w);
    bias_perm_kernel<<<4, 256>>>(W_b, Wv_b);
    // merged projections (z: 0=K,1=Q,2=V)
    proj_kernel<<<dim3(8,64,3), blk, DYN_PR>>>();
    // scores + head-softmax
    score_softmax_kernel<<<dim3(L_/64, L_/64, B_), blk, DYN_SC>>>();
    // attn^T @ V -> O^T fp16
    av_kernel<<<dim3(L_/128, NH, B_), blk, DYN_AV>>>();
    // final projection
    final_kernel<<<dim3(2,64), blk, DYN_FN>>>(Wo_b, out);
}